// round 10
// baseline (speedup 1.0000x reference)
#include <cuda_runtime.h>
#include <cstdint>

// ---------------------------------------------------------------------------
// PointNet++ encoder on GB300 (base sm_103 PTX: mma.sync + cp.async only).
// FPS / ball-query / gathers: exact fp32 (bitwise-match indices vs JAX ref).
// Stage-1 MLP (gather + K=3 layer + 2 mma layers + pool): single fused kernel.
// Stage-2/3 MLP layers: mma.sync m16n8k8 tf32, 3-term fp32 emulation,
// cp.async double buffering, pool fused into final layers.
// ---------------------------------------------------------------------------

#define BB   32
#define N1   4096
#define S1   256
#define S2   128
#define NS   32

__device__ float g_scr0[262144 * 128];   // 134 MB
__device__ float g_scr1[262144 * 128];   // 134 MB
__device__ float g_f1[BB * S1 * 128];
__device__ float g_f2[BB * S2 * 256];
__device__ float g_nx1[BB * S1 * 3];
__device__ float g_nx2[BB * S2 * 3];
__device__ int   g_g1[BB * S1 * NS];
__device__ int   g_g2[BB * S2 * NS];
__device__ float g_x3[BB * S2 * 288];
__device__ float g_w2p[128 * 160];
__device__ float g_w3p[256 * 288];

__device__ __forceinline__ float tf32r(float x) {
    float r;
    asm("cvt.rna.tf32.f32 %0, %1;" : "=f"(r) : "f"(x));
    return r;
}
__device__ __forceinline__ uint32_t smem_u32(const void* p) {
    uint32_t a;
    asm("{ .reg .u64 t; cvta.to.shared.u64 t, %1; cvt.u32.u64 %0, t; }"
        : "=r"(a) : "l"(p));
    return a;
}
__device__ __forceinline__ void cp16(uint32_t dst, const void* src) {
    asm volatile("cp.async.ca.shared.global [%0], [%1], 16;"
                 :: "r"(dst), "l"(src) : "memory");
}
#define CP_COMMIT() asm volatile("cp.async.commit_group;" ::: "memory")
#define CP_WAIT1()  asm volatile("cp.async.wait_group 1;" ::: "memory")

#define MMA_TF32(c, a, b0, b1)                                                \
    asm volatile(                                                             \
        "mma.sync.aligned.m16n8k8.row.col.f32.tf32.tf32.f32 "                 \
        "{%0,%1,%2,%3}, {%4,%5,%6,%7}, {%8,%9}, {%0,%1,%2,%3};"               \
        : "+f"((c)[0]), "+f"((c)[1]), "+f"((c)[2]), "+f"((c)[3])              \
        : "r"((a)[0]), "r"((a)[1]), "r"((a)[2]), "r"((a)[3]),                 \
          "r"(b0), "r"(b1))

// Load A fragment (2 m-tiles) from smem row-major [stride ST] and split hi/lo.
template <int ST>
__device__ __forceinline__ void frag_a_split(
    const float* s_a, int wm, int g, int ck, uint32_t ah[2][4], uint32_t al[2][4])
{
#pragma unroll
    for (int mt = 0; mt < 2; mt++) {
        int r0 = wm + mt * 16 + g;
        float a0 = s_a[r0 * ST + ck];
        float a1 = s_a[(r0 + 8) * ST + ck];
        float a2 = s_a[r0 * ST + ck + 4];
        float a3 = s_a[(r0 + 8) * ST + ck + 4];
        float h0 = tf32r(a0), h1 = tf32r(a1), h2 = tf32r(a2), h3 = tf32r(a3);
        ah[mt][0] = __float_as_uint(h0);
        ah[mt][1] = __float_as_uint(h1);
        ah[mt][2] = __float_as_uint(h2);
        ah[mt][3] = __float_as_uint(h3);
        al[mt][0] = __float_as_uint(tf32r(a0 - h0));
        al[mt][1] = __float_as_uint(tf32r(a1 - h1));
        al[mt][2] = __float_as_uint(tf32r(a2 - h2));
        al[mt][3] = __float_as_uint(tf32r(a3 - h3));
    }
}

// ---------------------------------------------------------------------------
// FPS stage 1 (bitwise exact vs reference)
// ---------------------------------------------------------------------------
template <int N, int NPTS, int THREADS>
__global__ void __launch_bounds__(THREADS) fps_kernel(
    const float* __restrict__ xyz_all, float* __restrict__ new_xyz)
{
    constexpr int PPT = N / THREADS;
    const int b = blockIdx.x;
    const int t = threadIdx.x;
    const float* xyz = xyz_all + (size_t)b * N * 3;

    float px[PPT], py[PPT], pz[PPT], md[PPT];
#pragma unroll
    for (int j = 0; j < PPT; j++) {
        int i = t + j * THREADS;
        px[j] = xyz[i * 3 + 0];
        py[j] = xyz[i * 3 + 1];
        pz[j] = xyz[i * 3 + 2];
        md[j] = 1e10f;
    }

    __shared__ unsigned long long wred[THREADS / 32];
    __shared__ int s_last;

    int last = 0;
    for (int it = 0; it < NPTS; it++) {
        float lx = __ldg(&xyz[last * 3 + 0]);
        float ly = __ldg(&xyz[last * 3 + 1]);
        float lz = __ldg(&xyz[last * 3 + 2]);
        if (t == 0) {
            float* o = new_xyz + (size_t)(b * NPTS + it) * 3;
            o[0] = lx; o[1] = ly; o[2] = lz;
        }
        unsigned long long best = 0ull;
#pragma unroll
        for (int j = 0; j < PPT; j++) {
            float dx = px[j] - lx, dy = py[j] - ly, dz = pz[j] - lz;
            float d = __fadd_rn(__fadd_rn(__fmul_rn(dx, dx), __fmul_rn(dy, dy)),
                                __fmul_rn(dz, dz));
            float m = fminf(md[j], d);
            md[j] = m;
            unsigned long long key =
                (((unsigned long long)__float_as_uint(m)) << 32) |
                (unsigned)(0xFFFFFFFFu - (unsigned)(t + j * THREADS));
            best = (key > best) ? key : best;
        }
#pragma unroll
        for (int off = 16; off > 0; off >>= 1) {
            unsigned long long o = __shfl_down_sync(0xffffffffu, best, off);
            best = (o > best) ? o : best;
        }
        if ((t & 31) == 0) wred[t >> 5] = best;
        __syncthreads();
        if (t < 32) {
            unsigned long long v = (t < THREADS / 32) ? wred[t] : 0ull;
#pragma unroll
            for (int off = 16; off > 0; off >>= 1) {
                unsigned long long o = __shfl_down_sync(0xffffffffu, v, off);
                v = (o > v) ? o : v;
            }
            if (t == 0)
                s_last = (int)(0xFFFFFFFFu - (unsigned)(v & 0xFFFFFFFFull));
        }
        __syncthreads();
        last = s_last;
    }
}

// ---------------------------------------------------------------------------
// Stage-1 ball query: 1024 threads, 8 blocks/batch, 32 warps = 32 centers
// per cloud staging. Identical per-center arithmetic/order -> exact indices.
// ---------------------------------------------------------------------------
__global__ void __launch_bounds__(1024) ballq1_smem(
    const float* __restrict__ xyz_all, const float* __restrict__ centers,
    float R2, int* __restrict__ out)
{
    extern __shared__ float sm[];
    float* sx = sm;
    float* sy = sm + N1;
    float* sz = sm + 2 * N1;
    int* buf = (int*)(sm + 3 * N1);          // [32][32]

    const int b = blockIdx.x >> 3;
    const int grp = blockIdx.x & 7;
    const float* xyz = xyz_all + (size_t)b * N1 * 3;
    for (int i = threadIdx.x; i < N1; i += 1024) {
        sx[i] = xyz[i * 3 + 0];
        sy[i] = xyz[i * 3 + 1];
        sz[i] = xyz[i * 3 + 2];
    }
    __syncthreads();

    const int wid = threadIdx.x >> 5, lane = threadIdx.x & 31;
    int* mybuf = buf + wid * 32;
    const int s = grp * 32 + wid;
    const int gw = b * S1 + s;
    const float cx = centers[gw * 3 + 0];
    const float cy = centers[gw * 3 + 1];
    const float cz = centers[gw * 3 + 2];
    int cnt = 0;
    for (int base = 0; base < N1; base += 32) {
        int p = base + lane;
        float dx = sx[p] - cx;
        float dy = sy[p] - cy;
        float dz = sz[p] - cz;
        float d2 = __fadd_rn(__fadd_rn(__fmul_rn(dx, dx), __fmul_rn(dy, dy)),
                             __fmul_rn(dz, dz));
        bool pred = d2 < R2;
        unsigned mask = __ballot_sync(0xffffffffu, pred);
        if (pred) {
            int pos = cnt + __popc(mask & ((1u << lane) - 1u));
            if (pos < NS) mybuf[pos] = p;
        }
        cnt += __popc(mask);
        if (cnt >= NS) break;
    }
    __syncwarp();
    int nv = cnt < NS ? cnt : NS;
    int first = (cnt > 0) ? mybuf[0] : 0;
    int val = (lane < nv) ? mybuf[lane] : first;
    out[(size_t)gw * NS + lane] = val;
}

// ---------------------------------------------------------------------------
// Fused FPS stage 2 + ball query 2 (one block per batch, smem-resident).
// Same math/order as separate kernels -> exact indices.
// ---------------------------------------------------------------------------
__global__ void __launch_bounds__(256) fps2_ballq2(
    const float* __restrict__ xyz_all, float* __restrict__ new_xyz,
    float R2, int* __restrict__ out)
{
    __shared__ float s_px[S1], s_py[S1], s_pz[S1];
    __shared__ float s_cx[S2], s_cy[S2], s_cz[S2];
    __shared__ unsigned long long wred[8];
    __shared__ int s_last;
    __shared__ int buf[8][32];

    const int b = blockIdx.x;
    const int t = threadIdx.x;
    const float* xyz = xyz_all + (size_t)b * S1 * 3;

    float px = xyz[t * 3 + 0];
    float py = xyz[t * 3 + 1];
    float pz = xyz[t * 3 + 2];
    s_px[t] = px; s_py[t] = py; s_pz[t] = pz;
    float md = 1e10f;

    int last = 0;
    for (int it = 0; it < S2; it++) {
        float lx = __ldg(&xyz[last * 3 + 0]);
        float ly = __ldg(&xyz[last * 3 + 1]);
        float lz = __ldg(&xyz[last * 3 + 2]);
        if (t == 0) {
            float* o = new_xyz + (size_t)(b * S2 + it) * 3;
            o[0] = lx; o[1] = ly; o[2] = lz;
            s_cx[it] = lx; s_cy[it] = ly; s_cz[it] = lz;
        }
        float dx = px - lx, dy = py - ly, dz = pz - lz;
        float d = __fadd_rn(__fadd_rn(__fmul_rn(dx, dx), __fmul_rn(dy, dy)),
                            __fmul_rn(dz, dz));
        md = fminf(md, d);
        unsigned long long best =
            (((unsigned long long)__float_as_uint(md)) << 32) |
            (unsigned)(0xFFFFFFFFu - (unsigned)t);
#pragma unroll
        for (int off = 16; off > 0; off >>= 1) {
            unsigned long long o = __shfl_down_sync(0xffffffffu, best, off);
            best = (o > best) ? o : best;
        }
        if ((t & 31) == 0) wred[t >> 5] = best;
        __syncthreads();
        if (t < 32) {
            unsigned long long v = (t < 8) ? wred[t] : 0ull;
#pragma unroll
            for (int off = 16; off > 0; off >>= 1) {
                unsigned long long o = __shfl_down_sync(0xffffffffu, v, off);
                v = (o > v) ? o : v;
            }
            if (t == 0)
                s_last = (int)(0xFFFFFFFFu - (unsigned)(v & 0xFFFFFFFFull));
        }
        __syncthreads();
        last = s_last;
    }

    // ball query from smem: 8 warps x 16 centers
    const int wid = t >> 5, lane = t & 31;
    int* mybuf = buf[wid];
    for (int ci = 0; ci < 16; ci++) {
        const int s = wid * 16 + ci;
        const float cx = s_cx[s], cy = s_cy[s], cz = s_cz[s];
        int cnt = 0;
        for (int base = 0; base < S1; base += 32) {
            int p = base + lane;
            float dx = s_px[p] - cx;
            float dy = s_py[p] - cy;
            float dz = s_pz[p] - cz;
            float d2 = __fadd_rn(__fadd_rn(__fmul_rn(dx, dx), __fmul_rn(dy, dy)),
                                 __fmul_rn(dz, dz));
            bool pred = d2 < R2;
            unsigned mask = __ballot_sync(0xffffffffu, pred);
            if (pred) {
                int pos = cnt + __popc(mask & ((1u << lane) - 1u));
                if (pos < NS) mybuf[pos] = p;
            }
            cnt += __popc(mask);
            if (cnt >= NS) break;
        }
        __syncwarp();
        int nv = cnt < NS ? cnt : NS;
        int first = (cnt > 0) ? mybuf[0] : 0;
        int val = (lane < nv) ? mybuf[lane] : first;
        out[((size_t)(b * S2 + s)) * NS + lane] = val;
        __syncwarp();
    }
}

// ---------------------------------------------------------------------------
// Fused stage-1 MLP: gather + (3->64) + (64->64) + (64->128) + 32-row maxpool.
// One CTA = 128 gathered rows = 4 ball groups. Activations live in smem.
// Accumulation orders identical to the per-layer kernels -> bitwise-same.
// ---------------------------------------------------------------------------
__global__ void __launch_bounds__(256) fused_stage1(
    const float* __restrict__ data,
    const float* __restrict__ w0, const float* __restrict__ b0,
    const float* __restrict__ w1, const float* __restrict__ b1,
    const float* __restrict__ w2, const float* __restrict__ b2,
    float* __restrict__ f1out)
{
    extern __shared__ float sm[];
    float* s_x  = sm;                    // 128*4
    float* s_w1 = sm + 512;              // 64*68
    float* s_w2 = s_w1 + 64 * 68;        // 128*68
    float* s_h0 = s_w2 + 128 * 68;       // 128*68
    float* s_h1 = s_h0 + 128 * 68;       // 128*68

    const int tid = threadIdx.x;
    const int wid = tid >> 5, lane = tid & 31;
    const int g = lane >> 2, tg = lane & 3;
    const int wm = (wid & 3) * 32;
    const int m0 = blockIdx.x * 128;

    for (int i = tid; i < 64 * 64; i += 256)
        s_w1[(i >> 6) * 68 + (i & 63)] = w1[i];
    for (int i = tid; i < 128 * 64; i += 256)
        s_w2[(i >> 6) * 68 + (i & 63)] = w2[i];

    if (tid < 128) {
        int r = m0 + tid;
        int c = r >> 5;
        int b = c >> 8;
        int gi = g_g1[r];
        const float* p = data + ((size_t)b * N1 + gi) * 3;
        const float* ctr = g_nx1 + (size_t)c * 3;
        s_x[tid * 4 + 0] = p[0] - ctr[0];
        s_x[tid * 4 + 1] = p[1] - ctr[1];
        s_x[tid * 4 + 2] = p[2] - ctr[2];
    }
    __syncthreads();

    // layer0: exact fp32 (same fmaf chain as the previous SGEMM)
    for (int idx = tid; idx < 128 * 64; idx += 256) {
        int r = idx >> 6, o = idx & 63;
        float acc = 0.f;
        acc = fmaf(s_x[r * 4 + 0], __ldg(&w0[o * 3 + 0]), acc);
        acc = fmaf(s_x[r * 4 + 1], __ldg(&w0[o * 3 + 1]), acc);
        acc = fmaf(s_x[r * 4 + 2], __ldg(&w0[o * 3 + 2]), acc);
        s_h0[r * 68 + o] = fmaxf(acc + __ldg(&b0[o]), 0.f);
    }
    __syncthreads();

    // layer1: 128x64 @ 64x64^T, warp tile 32x32 (NTW=4)
    {
        const int wn = (wid >> 2) * 32;
        float acc[2][4][4];
#pragma unroll
        for (int mt = 0; mt < 2; mt++)
#pragma unroll
            for (int nt = 0; nt < 4; nt++)
#pragma unroll
                for (int j = 0; j < 4; j++) acc[mt][nt][j] = 0.f;

        for (int kc = 0; kc < 2; kc++) {
#pragma unroll
            for (int kk = 0; kk < 4; kk++) {
                const int ck = kc * 32 + kk * 8 + tg;
                uint32_t ah[2][4], al[2][4];
                frag_a_split<68>(s_h0, wm, g, ck, ah, al);
#pragma unroll
                for (int nt = 0; nt < 4; nt++) {
                    int n = wn + nt * 8 + g;
                    float b0v = s_w1[n * 68 + ck];
                    float b1v = s_w1[n * 68 + ck + 4];
                    float hb0 = tf32r(b0v), hb1 = tf32r(b1v);
                    uint32_t bh0 = __float_as_uint(hb0);
                    uint32_t bh1 = __float_as_uint(hb1);
                    uint32_t bl0 = __float_as_uint(tf32r(b0v - hb0));
                    uint32_t bl1 = __float_as_uint(tf32r(b1v - hb1));
#pragma unroll
                    for (int mt = 0; mt < 2; mt++) {
                        MMA_TF32(acc[mt][nt], ah[mt], bh0, bh1);
                        MMA_TF32(acc[mt][nt], ah[mt], bl0, bl1);
                        MMA_TF32(acc[mt][nt], al[mt], bh0, bh1);
                    }
                }
            }
        }
        __syncthreads();   // all reads of s_h0 done before overwrite concerns
#pragma unroll
        for (int mt = 0; mt < 2; mt++) {
#pragma unroll
            for (int nt = 0; nt < 4; nt++) {
                int row = wm + mt * 16 + g;
                int col = wn + nt * 8 + 2 * tg;
                s_h1[row * 68 + col] =
                    fmaxf(acc[mt][nt][0] + __ldg(&b1[col]), 0.f);
                s_h1[row * 68 + col + 1] =
                    fmaxf(acc[mt][nt][1] + __ldg(&b1[col + 1]), 0.f);
                s_h1[(row + 8) * 68 + col] =
                    fmaxf(acc[mt][nt][2] + __ldg(&b1[col]), 0.f);
                s_h1[(row + 8) * 68 + col + 1] =
                    fmaxf(acc[mt][nt][3] + __ldg(&b1[col + 1]), 0.f);
            }
        }
    }
    __syncthreads();

    // layer2: 128x64 @ 128x64^T, warp tile 32x64 (NTW=8) + fused 32-row pool
    {
        const int wn = (wid >> 2) * 64;
        float acc[2][8][4];
#pragma unroll
        for (int mt = 0; mt < 2; mt++)
#pragma unroll
            for (int nt = 0; nt < 8; nt++)
#pragma unroll
                for (int j = 0; j < 4; j++) acc[mt][nt][j] = 0.f;

        for (int kc = 0; kc < 2; kc++) {
#pragma unroll
            for (int kk = 0; kk < 4; kk++) {
                const int ck = kc * 32 + kk * 8 + tg;
                uint32_t ah[2][4], al[2][4];
                frag_a_split<68>(s_h1, wm, g, ck, ah, al);
#pragma unroll
                for (int nt = 0; nt < 8; nt++) {
                    int n = wn + nt * 8 + g;
                    float b0v = s_w2[n * 68 + ck];
                    float b1v = s_w2[n * 68 + ck + 4];
                    float hb0 = tf32r(b0v), hb1 = tf32r(b1v);
                    uint32_t bh0 = __float_as_uint(hb0);
                    uint32_t bh1 = __float_as_uint(hb1);
                    uint32_t bl0 = __float_as_uint(tf32r(b0v - hb0));
                    uint32_t bl1 = __float_as_uint(tf32r(b1v - hb1));
#pragma unroll
                    for (int mt = 0; mt < 2; mt++) {
                        MMA_TF32(acc[mt][nt], ah[mt], bh0, bh1);
                        MMA_TF32(acc[mt][nt], ah[mt], bl0, bl1);
                        MMA_TF32(acc[mt][nt], al[mt], bh0, bh1);
                    }
                }
            }
        }
        // pool over the warp's 32 rows (one ball group)
#pragma unroll
        for (int nt = 0; nt < 8; nt++) {
            float v0 = fmaxf(fmaxf(acc[0][nt][0], acc[0][nt][2]),
                             fmaxf(acc[1][nt][0], acc[1][nt][2]));
            float v1 = fmaxf(fmaxf(acc[0][nt][1], acc[0][nt][3]),
                             fmaxf(acc[1][nt][1], acc[1][nt][3]));
#pragma unroll
            for (int off = 4; off < 32; off <<= 1) {
                v0 = fmaxf(v0, __shfl_xor_sync(0xffffffffu, v0, off));
                v1 = fmaxf(v1, __shfl_xor_sync(0xffffffffu, v1, off));
            }
            if (g == 0) {
                int center = blockIdx.x * 4 + (wid & 3);
                int col = wn + nt * 8 + 2 * tg;
                f1out[(size_t)center * 128 + col] =
                    fmaxf(v0 + __ldg(&b2[col]), 0.f);
                f1out[(size_t)center * 128 + col + 1] =
                    fmaxf(v1 + __ldg(&b2[col + 1]), 0.f);
            }
        }
    }
}

// ---------------------------------------------------------------------------
// Gathers / concat / weight pads
// ---------------------------------------------------------------------------
__global__ void gather2_kernel(float* __restrict__ x2)
{
    int r = blockIdx.x * 4 + (threadIdx.x >> 5);
    int lane = threadIdx.x & 31;
    int c = r >> 5;
    int b = c >> 7;
    int j = g_g2[r];
    const float* src = g_nx1 + ((size_t)b * S1 + j) * 3;
    const float* ctr = g_nx2 + (size_t)c * 3;
    const float* f = g_f1 + ((size_t)b * S1 + j) * 128;
    float* dst = x2 + (size_t)r * 160;
    for (int col = lane; col < 160; col += 32)
        dst[col] = (col < 3) ? (src[col] - ctr[col])
                             : (col < 131 ? f[col - 3] : 0.f);
}

__global__ void concat3_kernel(float* __restrict__ x3)
{
    int t = blockIdx.x * blockDim.x + threadIdx.x;
    if (t >= BB * S2 * 288) return;
    int r = t / 288, col = t - r * 288;
    x3[t] = (col < 3) ? g_nx2[(size_t)r * 3 + col]
                      : (col < 259 ? g_f2[(size_t)r * 256 + (col - 3)] : 0.f);
}

__global__ void padw_kernel(const float* __restrict__ w, float* __restrict__ o,
                            int n, int kin, int kout)
{
    int t = blockIdx.x * blockDim.x + threadIdx.x;
    if (t >= n * kout) return;
    int r = t / kout, c = t - r * kout;
    o[t] = (c < kin) ? w[r * kin + c] : 0.f;
}

// ---------------------------------------------------------------------------
// Shared mma mainloop for global-memory GEMMs (cp.async double-buffered).
// ---------------------------------------------------------------------------
template <int BN, int NTW>
__device__ __forceinline__ void mma_mainloop(
    const float* __restrict__ A, const float* __restrict__ W,
    int K, int m0, int n0, float* smf, uint32_t smbase,
    int tid, int wid, int lane, int g, int tg, int wm, int wn,
    float acc[2][NTW][4])
{
    constexpr int SLOT = (128 + BN) * 36;
    const int KC = K >> 5;

    auto prefetch = [&](int kc, int s) {
        const uint32_t sb = smbase + (uint32_t)(s * SLOT) * 4u;
#pragma unroll
        for (int i = 0; i < 4; i++) {
            int seg = tid + i * 256;
            int r = seg >> 3, c16 = seg & 7;
            cp16(sb + (uint32_t)(r * 36 + c16 * 4) * 4u,
                 A + (size_t)(m0 + r) * K + kc * 32 + c16 * 4);
        }
#pragma unroll
        for (int i = 0; i < BN / 32; i++) {
            int seg = tid + i * 256;
            int r = seg >> 3, c16 = seg & 7;
            cp16(sb + (uint32_t)((128 + r) * 36 + c16 * 4) * 4u,
                 W + (size_t)(n0 + r) * K + kc * 32 + c16 * 4);
        }
    };

    prefetch(0, 0);
    CP_COMMIT();

    for (int kc = 0; kc < KC; kc++) {
        if (kc + 1 < KC) prefetch(kc + 1, (kc + 1) & 1);
        CP_COMMIT();
        CP_WAIT1();
        __syncthreads();

        const float* s_a = smf + (kc & 1) * SLOT;
        const float* s_w = s_a + 128 * 36;

#pragma unroll
        for (int kk = 0; kk < 4; kk++) {
            const int ck = kk * 8 + tg;
            uint32_t ah[2][4], al[2][4];
            frag_a_split<36>(s_a, wm, g, ck, ah, al);
#pragma unroll
            for (int nt = 0; nt < NTW; nt++) {
                int n = wn + nt * 8 + g;
                float b0 = s_w[n * 36 + ck];
                float b1 = s_w[n * 36 + ck + 4];
                float hb0 = tf32r(b0), hb1 = tf32r(b1);
                uint32_t bh0 = __float_as_uint(hb0);
                uint32_t bh1 = __float_as_uint(hb1);
                uint32_t bl0 = __float_as_uint(tf32r(b0 - hb0));
                uint32_t bl1 = __float_as_uint(tf32r(b1 - hb1));
#pragma unroll
                for (int mt = 0; mt < 2; mt++) {
                    MMA_TF32(acc[mt][nt], ah[mt], bh0, bh1);
                    MMA_TF32(acc[mt][nt], ah[mt], bl0, bl1);
                    MMA_TF32(acc[mt][nt], al[mt], bh0, bh1);
                }
            }
        }
        __syncthreads();
    }
}

template <int BN>
__global__ void __launch_bounds__(256) gemm_mma(
    const float* __restrict__ A, const float* __restrict__ W,
    const float* __restrict__ bias, float* __restrict__ C,
    int M, int N, int K)
{
    constexpr int NTW = BN / 16;
    extern __shared__ float smf[];
    const int tid = threadIdx.x;
    const int wid = tid >> 5, lane = tid & 31;
    const int g = lane >> 2, tg = lane & 3;
    const int wm = (wid & 3) * 32;
    const int wn = (wid >> 2) * (BN / 2);
    const int m0 = blockIdx.x * 128;
    const int n0 = blockIdx.y * BN;

    float acc[2][NTW][4];
#pragma unroll
    for (int mt = 0; mt < 2; mt++)
#pragma unroll
        for (int nt = 0; nt < NTW; nt++)
#pragma unroll
            for (int j = 0; j < 4; j++) acc[mt][nt][j] = 0.f;

    mma_mainloop<BN, NTW>(A, W, K, m0, n0, smf, smem_u32(smf),
                          tid, wid, lane, g, tg, wm, wn, acc);

#pragma unroll
    for (int mt = 0; mt < 2; mt++) {
#pragma unroll
        for (int nt = 0; nt < NTW; nt++) {
            int row = m0 + wm + mt * 16 + g;
            int col = n0 + wn + nt * 8 + 2 * tg;
            float b0 = __ldg(&bias[col]);
            float b1 = __ldg(&bias[col + 1]);
            float2 o0, o1;
            o0.x = fmaxf(acc[mt][nt][0] + b0, 0.f);
            o0.y = fmaxf(acc[mt][nt][1] + b1, 0.f);
            o1.x = fmaxf(acc[mt][nt][2] + b0, 0.f);
            o1.y = fmaxf(acc[mt][nt][3] + b1, 0.f);
            *reinterpret_cast<float2*>(C + (size_t)row * N + col) = o0;
            *reinterpret_cast<float2*>(C + (size_t)(row + 8) * N + col) = o1;
        }
    }
}

template <int BN, int PR>
__global__ void __launch_bounds__(256) gemm_mma_pool(
    const float* __restrict__ A, const float* __restrict__ W,
    const float* __restrict__ bias, float* __restrict__ dst,
    int M, int N, int K)
{
    constexpr int NTW = BN / 16;
    extern __shared__ float smf[];
    __shared__ float sbuf[4][BN];
    const int tid = threadIdx.x;
    const int wid = tid >> 5, lane = tid & 31;
    const int g = lane >> 2, tg = lane & 3;
    const int wm = (wid & 3) * 32;
    const int wn = (wid >> 2) * (BN / 2);
    const int m0 = blockIdx.x * 128;
    const int n0 = blockIdx.y * BN;

    float acc[2][NTW][4];
#pragma unroll
    for (int mt = 0; mt < 2; mt++)
#pragma unroll
        for (int nt = 0; nt < NTW; nt++)
#pragma unroll
            for (int j = 0; j < 4; j++) acc[mt][nt][j] = 0.f;

    mma_mainloop<BN, NTW>(A, W, K, m0, n0, smf, smem_u32(smf),
                          tid, wid, lane, g, tg, wm, wn, acc);

#pragma unroll
    for (int nt = 0; nt < NTW; nt++) {
        float v0 = fmaxf(fmaxf(acc[0][nt][0], acc[0][nt][2]),
                         fmaxf(acc[1][nt][0], acc[1][nt][2]));
        float v1 = fmaxf(fmaxf(acc[0][nt][1], acc[0][nt][3]),
                         fmaxf(acc[1][nt][1], acc[1][nt][3]));
#pragma unroll
        for (int off = 4; off < 32; off <<= 1) {
            v0 = fmaxf(v0, __shfl_xor_sync(0xffffffffu, v0, off));
            v1 = fmaxf(v1, __shfl_xor_sync(0xffffffffu, v1, off));
        }
        if (g == 0) {
            int lcol = wn + nt * 8 + 2 * tg;
            if (PR == 32) {
                int center = blockIdx.x * 4 + (wid & 3);
                int col = n0 + lcol;
                dst[(size_t)center * N + col] =
                    fmaxf(v0 + __ldg(&bias[col]), 0.f);
                dst[(size_t)center * N + col + 1] =
                    fmaxf(v1 + __ldg(&bias[col + 1]), 0.f);
            } else {
                sbuf[wid & 3][lcol] = v0;
                sbuf[wid & 3][lcol + 1] = v1;
            }
        }
    }
    if (PR == 128) {
        __syncthreads();
        if (tid < BN) {
            float m = fmaxf(fmaxf(sbuf[0][tid], sbuf[1][tid]),
                            fmaxf(sbuf[2][tid], sbuf[3][tid]));
            int col = n0 + tid;
            dst[(size_t)blockIdx.x * N + col] =
                fmaxf(m + __ldg(&bias[col]), 0.f);
        }
    }
}

// ---------------------------------------------------------------------------
static void run_mma(const float* A, const float* W, const float* bias,
                    float* C, int M, int N, int K)
{
    if (N % 128 == 0) {
        const int smem = 2 * (128 + 128) * 36 * 4;
        cudaFuncSetAttribute(gemm_mma<128>,
                             cudaFuncAttributeMaxDynamicSharedMemorySize, smem);
        dim3 g(M / 128, N / 128);
        gemm_mma<128><<<g, 256, smem>>>(A, W, bias, C, M, N, K);
    } else {
        const int smem = 2 * (128 + 64) * 36 * 4;
        cudaFuncSetAttribute(gemm_mma<64>,
                             cudaFuncAttributeMaxDynamicSharedMemorySize, smem);
        dim3 g(M / 128, N / 64);
        gemm_mma<64><<<g, 256, smem>>>(A, W, bias, C, M, N, K);
    }
}

template <int PR>
static void run_mma_pool(const float* A, const float* W, const float* bias,
                         float* dst, int M, int N, int K)
{
    const int smem = 2 * (128 + 128) * 36 * 4;
    cudaFuncSetAttribute(gemm_mma_pool<128, PR>,
                         cudaFuncAttributeMaxDynamicSharedMemorySize, smem);
    dim3 g(M / 128, N / 128);
    gemm_mma_pool<128, PR><<<g, 256, smem>>>(A, W, bias, dst, M, N, K);
}

extern "C" void kernel_launch(void* const* d_in, const int* in_sizes, int n_in,
                              void* d_out, int out_size)
{
    (void)in_sizes; (void)n_in; (void)out_size;
    const float* data = (const float*)d_in[0];
    const float *w[9], *bi[9];
    for (int i = 0; i < 9; i++) {
        w[i]  = (const float*)d_in[1 + 2 * i];
        bi[i] = (const float*)d_in[2 + 2 * i];
    }

    float *scr0, *scr1, *f1, *f2, *nx1, *nx2, *x3, *w2p, *w3p;
    int *g1, *g2;
    cudaGetSymbolAddress((void**)&scr0, g_scr0);
    cudaGetSymbolAddress((void**)&scr1, g_scr1);
    cudaGetSymbolAddress((void**)&f1, g_f1);
    cudaGetSymbolAddress((void**)&f2, g_f2);
    cudaGetSymbolAddress((void**)&nx1, g_nx1);
    cudaGetSymbolAddress((void**)&nx2, g_nx2);
    cudaGetSymbolAddress((void**)&g1, g_g1);
    cudaGetSymbolAddress((void**)&g2, g_g2);
    cudaGetSymbolAddress((void**)&x3, g_x3);
    cudaGetSymbolAddress((void**)&w2p, g_w2p);
    cudaGetSymbolAddress((void**)&w3p, g_w3p);

    const float R2a = (float)(0.2 * 0.2);
    const float R2b = (float)(0.4 * 0.4);

    padw_kernel<<<(128 * 160 + 255) / 256, 256>>>(w[3], w2p, 128, 131, 160);
    padw_kernel<<<(256 * 288 + 255) / 256, 256>>>(w[6], w3p, 256, 259, 288);

    // ---- Stage 1 ----
    fps_kernel<N1, S1, 512><<<BB, 512>>>(data, nx1);
    {
        const int smem = 3 * N1 * 4 + 32 * 32 * 4;   // 53248
        cudaFuncSetAttribute(ballq1_smem,
                             cudaFuncAttributeMaxDynamicSharedMemorySize, smem);
        ballq1_smem<<<BB * 8, 1024, smem>>>(data, nx1, R2a, g1);
    }
    {
        const int smem = (512 + 64 * 68 + 3 * 128 * 68) * 4;   // 123904
        cudaFuncSetAttribute(fused_stage1,
                             cudaFuncAttributeMaxDynamicSharedMemorySize, smem);
        fused_stage1<<<(BB * S1 * NS) / 128, 256, smem>>>(
            data, w[0], bi[0], w[1], bi[1], w[2], bi[2], f1);
    }

    // ---- Stage 2 ----
    fps2_ballq2<<<BB, 256>>>(nx1, nx2, R2b, g2);
    gather2_kernel<<<(BB * S2 * NS) / 4, 128>>>(scr0);
    run_mma(scr0, w2p, bi[3], scr1, BB * S2 * NS, 128, 160);
    run_mma(scr1, w[4], bi[4], scr0, BB * S2 * NS, 128, 128);
    run_mma_pool<32>(scr0, w[5], bi[5], f2, BB * S2 * NS, 256, 128);

    // ---- Stage 3 ----
    concat3_kernel<<<(BB * S2 * 288 + 255) / 256, 256>>>(x3);
    run_mma(x3, w3p, bi[6], scr0, BB * S2, 256, 288);
    run_mma(scr0, w[7], bi[7], scr1, BB * S2, 512, 256);
    run_mma_pool<128>(scr1, w[8], bi[8], (float*)d_out, BB * S2, 1024, 512);
}

// round 11
// speedup vs baseline: 1.0197x; 1.0197x over previous
#include <cuda_runtime.h>
#include <cstdint>

// ---------------------------------------------------------------------------
// PointNet++ encoder on GB300 (base sm_103 PTX: mma.sync + cp.async only).
// FPS / ball-query / gathers: exact fp32 (bitwise-match indices vs JAX ref).
// MLP layers K>=32: mma.sync m16n8k8 tf32, 3-term fp32 emulation, raw-fp32
// smem, register-side hi/lo split, cp.async double buffering.
// Pool fused into final layer of each stage. Per-layer kernels (high occ).
// ---------------------------------------------------------------------------

#define BB   32
#define N1   4096
#define S1   256
#define S2   128
#define NS   32

__device__ float g_scr0[262144 * 128];   // 134 MB
__device__ float g_scr1[262144 * 128];   // 134 MB
__device__ float g_f1[BB * S1 * 128];
__device__ float g_f2[BB * S2 * 256];
__device__ float g_nx1[BB * S1 * 3];
__device__ float g_nx2[BB * S2 * 3];
__device__ int   g_g1[BB * S1 * NS];
__device__ int   g_g2[BB * S2 * NS];
__device__ float g_x3[BB * S2 * 288];
__device__ float g_w2p[128 * 160];
__device__ float g_w3p[256 * 288];

__device__ __forceinline__ float tf32r(float x) {
    float r;
    asm("cvt.rna.tf32.f32 %0, %1;" : "=f"(r) : "f"(x));
    return r;
}
__device__ __forceinline__ uint32_t smem_u32(const void* p) {
    uint32_t a;
    asm("{ .reg .u64 t; cvta.to.shared.u64 t, %1; cvt.u32.u64 %0, t; }"
        : "=r"(a) : "l"(p));
    return a;
}
__device__ __forceinline__ void cp16(uint32_t dst, const void* src) {
    asm volatile("cp.async.ca.shared.global [%0], [%1], 16;"
                 :: "r"(dst), "l"(src) : "memory");
}
#define CP_COMMIT() asm volatile("cp.async.commit_group;" ::: "memory")
#define CP_WAIT1()  asm volatile("cp.async.wait_group 1;" ::: "memory")

#define MMA_TF32(c, a, b0, b1)                                                \
    asm volatile(                                                             \
        "mma.sync.aligned.m16n8k8.row.col.f32.tf32.tf32.f32 "                 \
        "{%0,%1,%2,%3}, {%4,%5,%6,%7}, {%8,%9}, {%0,%1,%2,%3};"               \
        : "+f"((c)[0]), "+f"((c)[1]), "+f"((c)[2]), "+f"((c)[3])              \
        : "r"((a)[0]), "r"((a)[1]), "r"((a)[2]), "r"((a)[3]),                 \
          "r"(b0), "r"(b1))

template <int ST>
__device__ __forceinline__ void frag_a_split(
    const float* s_a, int wm, int g, int ck, uint32_t ah[2][4], uint32_t al[2][4])
{
#pragma unroll
    for (int mt = 0; mt < 2; mt++) {
        int r0 = wm + mt * 16 + g;
        float a0 = s_a[r0 * ST + ck];
        float a1 = s_a[(r0 + 8) * ST + ck];
        float a2 = s_a[r0 * ST + ck + 4];
        float a3 = s_a[(r0 + 8) * ST + ck + 4];
        float h0 = tf32r(a0), h1 = tf32r(a1), h2 = tf32r(a2), h3 = tf32r(a3);
        ah[mt][0] = __float_as_uint(h0);
        ah[mt][1] = __float_as_uint(h1);
        ah[mt][2] = __float_as_uint(h2);
        ah[mt][3] = __float_as_uint(h3);
        al[mt][0] = __float_as_uint(tf32r(a0 - h0));
        al[mt][1] = __float_as_uint(tf32r(a1 - h1));
        al[mt][2] = __float_as_uint(tf32r(a2 - h2));
        al[mt][3] = __float_as_uint(tf32r(a3 - h3));
    }
}

// ---------------------------------------------------------------------------
// FPS stage 1 (bitwise exact vs reference)
// ---------------------------------------------------------------------------
template <int N, int NPTS, int THREADS>
__global__ void __launch_bounds__(THREADS) fps_kernel(
    const float* __restrict__ xyz_all, float* __restrict__ new_xyz)
{
    constexpr int PPT = N / THREADS;
    const int b = blockIdx.x;
    const int t = threadIdx.x;
    const float* xyz = xyz_all + (size_t)b * N * 3;

    float px[PPT], py[PPT], pz[PPT], md[PPT];
#pragma unroll
    for (int j = 0; j < PPT; j++) {
        int i = t + j * THREADS;
        px[j] = xyz[i * 3 + 0];
        py[j] = xyz[i * 3 + 1];
        pz[j] = xyz[i * 3 + 2];
        md[j] = 1e10f;
    }

    __shared__ unsigned long long wred[THREADS / 32];
    __shared__ int s_last;

    int last = 0;
    for (int it = 0; it < NPTS; it++) {
        float lx = __ldg(&xyz[last * 3 + 0]);
        float ly = __ldg(&xyz[last * 3 + 1]);
        float lz = __ldg(&xyz[last * 3 + 2]);
        if (t == 0) {
            float* o = new_xyz + (size_t)(b * NPTS + it) * 3;
            o[0] = lx; o[1] = ly; o[2] = lz;
        }
        unsigned long long best = 0ull;
#pragma unroll
        for (int j = 0; j < PPT; j++) {
            float dx = px[j] - lx, dy = py[j] - ly, dz = pz[j] - lz;
            float d = __fadd_rn(__fadd_rn(__fmul_rn(dx, dx), __fmul_rn(dy, dy)),
                                __fmul_rn(dz, dz));
            float m = fminf(md[j], d);
            md[j] = m;
            unsigned long long key =
                (((unsigned long long)__float_as_uint(m)) << 32) |
                (unsigned)(0xFFFFFFFFu - (unsigned)(t + j * THREADS));
            best = (key > best) ? key : best;
        }
#pragma unroll
        for (int off = 16; off > 0; off >>= 1) {
            unsigned long long o = __shfl_down_sync(0xffffffffu, best, off);
            best = (o > best) ? o : best;
        }
        if ((t & 31) == 0) wred[t >> 5] = best;
        __syncthreads();
        if (t < 32) {
            unsigned long long v = (t < THREADS / 32) ? wred[t] : 0ull;
#pragma unroll
            for (int off = 16; off > 0; off >>= 1) {
                unsigned long long o = __shfl_down_sync(0xffffffffu, v, off);
                v = (o > v) ? o : v;
            }
            if (t == 0)
                s_last = (int)(0xFFFFFFFFu - (unsigned)(v & 0xFFFFFFFFull));
        }
        __syncthreads();
        last = s_last;
    }
}

// ---------------------------------------------------------------------------
// Stage-1 ball query: 1024 threads, 8 blocks/batch, 32 warps = 32 centers
// per cloud staging. Identical per-center arithmetic/order -> exact indices.
// ---------------------------------------------------------------------------
__global__ void __launch_bounds__(1024) ballq1_smem(
    const float* __restrict__ xyz_all, const float* __restrict__ centers,
    float R2, int* __restrict__ out)
{
    extern __shared__ float sm[];
    float* sx = sm;
    float* sy = sm + N1;
    float* sz = sm + 2 * N1;
    int* buf = (int*)(sm + 3 * N1);          // [32][32]

    const int b = blockIdx.x >> 3;
    const int grp = blockIdx.x & 7;
    const float* xyz = xyz_all + (size_t)b * N1 * 3;
    for (int i = threadIdx.x; i < N1; i += 1024) {
        sx[i] = xyz[i * 3 + 0];
        sy[i] = xyz[i * 3 + 1];
        sz[i] = xyz[i * 3 + 2];
    }
    __syncthreads();

    const int wid = threadIdx.x >> 5, lane = threadIdx.x & 31;
    int* mybuf = buf + wid * 32;
    const int s = grp * 32 + wid;
    const int gw = b * S1 + s;
    const float cx = centers[gw * 3 + 0];
    const float cy = centers[gw * 3 + 1];
    const float cz = centers[gw * 3 + 2];
    int cnt = 0;
    for (int base = 0; base < N1; base += 32) {
        int p = base + lane;
        float dx = sx[p] - cx;
        float dy = sy[p] - cy;
        float dz = sz[p] - cz;
        float d2 = __fadd_rn(__fadd_rn(__fmul_rn(dx, dx), __fmul_rn(dy, dy)),
                             __fmul_rn(dz, dz));
        bool pred = d2 < R2;
        unsigned mask = __ballot_sync(0xffffffffu, pred);
        if (pred) {
            int pos = cnt + __popc(mask & ((1u << lane) - 1u));
            if (pos < NS) mybuf[pos] = p;
        }
        cnt += __popc(mask);
        if (cnt >= NS) break;
    }
    __syncwarp();
    int nv = cnt < NS ? cnt : NS;
    int first = (cnt > 0) ? mybuf[0] : 0;
    int val = (lane < nv) ? mybuf[lane] : first;
    out[(size_t)gw * NS + lane] = val;
}

// ---------------------------------------------------------------------------
// Fused FPS stage 2 + ball query 2 (one block per batch, smem-resident).
// ---------------------------------------------------------------------------
__global__ void __launch_bounds__(256) fps2_ballq2(
    const float* __restrict__ xyz_all, float* __restrict__ new_xyz,
    float R2, int* __restrict__ out)
{
    __shared__ float s_px[S1], s_py[S1], s_pz[S1];
    __shared__ float s_cx[S2], s_cy[S2], s_cz[S2];
    __shared__ unsigned long long wred[8];
    __shared__ int s_last;
    __shared__ int buf[8][32];

    const int b = blockIdx.x;
    const int t = threadIdx.x;
    const float* xyz = xyz_all + (size_t)b * S1 * 3;

    float px = xyz[t * 3 + 0];
    float py = xyz[t * 3 + 1];
    float pz = xyz[t * 3 + 2];
    s_px[t] = px; s_py[t] = py; s_pz[t] = pz;
    float md = 1e10f;

    int last = 0;
    for (int it = 0; it < S2; it++) {
        float lx = __ldg(&xyz[last * 3 + 0]);
        float ly = __ldg(&xyz[last * 3 + 1]);
        float lz = __ldg(&xyz[last * 3 + 2]);
        if (t == 0) {
            float* o = new_xyz + (size_t)(b * S2 + it) * 3;
            o[0] = lx; o[1] = ly; o[2] = lz;
            s_cx[it] = lx; s_cy[it] = ly; s_cz[it] = lz;
        }
        float dx = px - lx, dy = py - ly, dz = pz - lz;
        float d = __fadd_rn(__fadd_rn(__fmul_rn(dx, dx), __fmul_rn(dy, dy)),
                            __fmul_rn(dz, dz));
        md = fminf(md, d);
        unsigned long long best =
            (((unsigned long long)__float_as_uint(md)) << 32) |
            (unsigned)(0xFFFFFFFFu - (unsigned)t);
#pragma unroll
        for (int off = 16; off > 0; off >>= 1) {
            unsigned long long o = __shfl_down_sync(0xffffffffu, best, off);
            best = (o > best) ? o : best;
        }
        if ((t & 31) == 0) wred[t >> 5] = best;
        __syncthreads();
        if (t < 32) {
            unsigned long long v = (t < 8) ? wred[t] : 0ull;
#pragma unroll
            for (int off = 16; off > 0; off >>= 1) {
                unsigned long long o = __shfl_down_sync(0xffffffffu, v, off);
                v = (o > v) ? o : v;
            }
            if (t == 0)
                s_last = (int)(0xFFFFFFFFu - (unsigned)(v & 0xFFFFFFFFull));
        }
        __syncthreads();
        last = s_last;
    }

    const int wid = t >> 5, lane = t & 31;
    int* mybuf = buf[wid];
    for (int ci = 0; ci < 16; ci++) {
        const int s = wid * 16 + ci;
        const float cx = s_cx[s], cy = s_cy[s], cz = s_cz[s];
        int cnt = 0;
        for (int base = 0; base < S1; base += 32) {
            int p = base + lane;
            float dx = s_px[p] - cx;
            float dy = s_py[p] - cy;
            float dz = s_pz[p] - cz;
            float d2 = __fadd_rn(__fadd_rn(__fmul_rn(dx, dx), __fmul_rn(dy, dy)),
                                 __fmul_rn(dz, dz));
            bool pred = d2 < R2;
            unsigned mask = __ballot_sync(0xffffffffu, pred);
            if (pred) {
                int pos = cnt + __popc(mask & ((1u << lane) - 1u));
                if (pos < NS) mybuf[pos] = p;
            }
            cnt += __popc(mask);
            if (cnt >= NS) break;
        }
        __syncwarp();
        int nv = cnt < NS ? cnt : NS;
        int first = (cnt > 0) ? mybuf[0] : 0;
        int val = (lane < nv) ? mybuf[lane] : first;
        out[((size_t)(b * S2 + s)) * NS + lane] = val;
        __syncwarp();
    }
}

// ---------------------------------------------------------------------------
// Gathers / concat / weight pads
// ---------------------------------------------------------------------------
__global__ void gather1_kernel(const float* __restrict__ data,
                               float* __restrict__ x1)
{
    int r = blockIdx.x * blockDim.x + threadIdx.x;
    if (r >= BB * S1 * NS) return;
    int c = r >> 5;
    int b = c >> 8;
    int g = g_g1[r];
    const float* p = data + ((size_t)b * N1 + g) * 3;
    const float* ctr = g_nx1 + (size_t)c * 3;
    float* o = x1 + (size_t)r * 3;
    o[0] = p[0] - ctr[0];
    o[1] = p[1] - ctr[1];
    o[2] = p[2] - ctr[2];
}

__global__ void gather2_kernel(float* __restrict__ x2)
{
    int r = blockIdx.x * 4 + (threadIdx.x >> 5);
    int lane = threadIdx.x & 31;
    int c = r >> 5;
    int b = c >> 7;
    int j = g_g2[r];
    const float* src = g_nx1 + ((size_t)b * S1 + j) * 3;
    const float* ctr = g_nx2 + (size_t)c * 3;
    const float* f = g_f1 + ((size_t)b * S1 + j) * 128;
    float* dst = x2 + (size_t)r * 160;
    for (int col = lane; col < 160; col += 32)
        dst[col] = (col < 3) ? (src[col] - ctr[col])
                             : (col < 131 ? f[col - 3] : 0.f);
}

__global__ void concat3_kernel(float* __restrict__ x3)
{
    int t = blockIdx.x * blockDim.x + threadIdx.x;
    if (t >= BB * S2 * 288) return;
    int r = t / 288, col = t - r * 288;
    x3[t] = (col < 3) ? g_nx2[(size_t)r * 3 + col]
                      : (col < 259 ? g_f2[(size_t)r * 256 + (col - 3)] : 0.f);
}

__global__ void padw_kernel(const float* __restrict__ w, float* __restrict__ o,
                            int n, int kin, int kout)
{
    int t = blockIdx.x * blockDim.x + threadIdx.x;
    if (t >= n * kout) return;
    int r = t / kout, c = t - r * kout;
    o[t] = (c < kin) ? w[r * kin + c] : 0.f;
}

// ---------------------------------------------------------------------------
// SGEMM for layer 1_0 (K=3, memory-bound)
// ---------------------------------------------------------------------------
__global__ void __launch_bounds__(256) gemm_bias_relu(
    const float* __restrict__ A, const float* __restrict__ W,
    const float* __restrict__ bias, float* __restrict__ C,
    int M, int N, int K, int lda)
{
    __shared__ float As[16][128];
    __shared__ float Ws[16][64];
    const int tid = threadIdx.x;
    const int ty = tid >> 4, tx = tid & 15;
    const int m0 = blockIdx.x * 128;
    const int n0 = blockIdx.y * 64;

    const int a_m = tid >> 1;
    const int a_k0 = (tid & 1) * 8;
    const int w_n = tid >> 2;
    const int w_k0 = (tid & 3) * 4;

    const float* Arow = A + (size_t)(m0 + a_m) * lda;
    const float* Wrow = W + (size_t)(n0 + w_n) * K;

    float acc[8][4];
#pragma unroll
    for (int i = 0; i < 8; i++)
#pragma unroll
        for (int j = 0; j < 4; j++) acc[i][j] = 0.f;

    for (int k0 = 0; k0 < K; k0 += 16) {
#pragma unroll
        for (int i = 0; i < 8; i++) {
            int k = k0 + a_k0 + i;
            As[a_k0 + i][a_m] = (k < K) ? Arow[k] : 0.f;
        }
#pragma unroll
        for (int i = 0; i < 4; i++) {
            int k = k0 + w_k0 + i;
            Ws[w_k0 + i][w_n] = (k < K) ? Wrow[k] : 0.f;
        }
        __syncthreads();
#pragma unroll
        for (int kk = 0; kk < 16; kk++) {
            float a[8], wv[4];
#pragma unroll
            for (int i = 0; i < 8; i++) a[i] = As[kk][ty * 8 + i];
#pragma unroll
            for (int j = 0; j < 4; j++) wv[j] = Ws[kk][tx * 4 + j];
#pragma unroll
            for (int i = 0; i < 8; i++)
#pragma unroll
                for (int j = 0; j < 4; j++)
                    acc[i][j] = fmaf(a[i], wv[j], acc[i][j]);
        }
        __syncthreads();
    }

    float bv[4];
#pragma unroll
    for (int j = 0; j < 4; j++) bv[j] = bias[n0 + tx * 4 + j];
#pragma unroll
    for (int i = 0; i < 8; i++) {
        int m = m0 + ty * 8 + i;
        float4 o;
        o.x = fmaxf(acc[i][0] + bv[0], 0.f);
        o.y = fmaxf(acc[i][1] + bv[1], 0.f);
        o.z = fmaxf(acc[i][2] + bv[2], 0.f);
        o.w = fmaxf(acc[i][3] + bv[3], 0.f);
        *reinterpret_cast<float4*>(C + (size_t)m * N + n0 + tx * 4) = o;
    }
}

// ---------------------------------------------------------------------------
// Shared mma mainloop (cp.async double-buffered), CTA tile 128 x BN, BK=32.
// ---------------------------------------------------------------------------
template <int BN, int NTW>
__device__ __forceinline__ void mma_mainloop(
    const float* __restrict__ A, const float* __restrict__ W,
    int K, int m0, int n0, float* smf, uint32_t smbase,
    int tid, int wid, int lane, int g, int tg, int wm, int wn,
    float acc[2][NTW][4])
{
    constexpr int SLOT = (128 + BN) * 36;
    const int KC = K >> 5;

    auto prefetch = [&](int kc, int s) {
        const uint32_t sb = smbase + (uint32_t)(s * SLOT) * 4u;
#pragma unroll
        for (int i = 0; i < 4; i++) {
            int seg = tid + i * 256;
            int r = seg >> 3, c16 = seg & 7;
            cp16(sb + (uint32_t)(r * 36 + c16 * 4) * 4u,
                 A + (size_t)(m0 + r) * K + kc * 32 + c16 * 4);
        }
#pragma unroll
        for (int i = 0; i < BN / 32; i++) {
            int seg = tid + i * 256;
            int r = seg >> 3, c16 = seg & 7;
            cp16(sb + (uint32_t)((128 + r) * 36 + c16 * 4) * 4u,
                 W + (size_t)(n0 + r) * K + kc * 32 + c16 * 4);
        }
    };

    prefetch(0, 0);
    CP_COMMIT();

    for (int kc = 0; kc < KC; kc++) {
        if (kc + 1 < KC) prefetch(kc + 1, (kc + 1) & 1);
        CP_COMMIT();
        CP_WAIT1();
        __syncthreads();

        const float* s_a = smf + (kc & 1) * SLOT;
        const float* s_w = s_a + 128 * 36;

#pragma unroll
        for (int kk = 0; kk < 4; kk++) {
            const int ck = kk * 8 + tg;
            uint32_t ah[2][4], al[2][4];
            frag_a_split<36>(s_a, wm, g, ck, ah, al);
#pragma unroll
            for (int nt = 0; nt < NTW; nt++) {
                int n = wn + nt * 8 + g;
                float b0 = s_w[n * 36 + ck];
                float b1 = s_w[n * 36 + ck + 4];
                float hb0 = tf32r(b0), hb1 = tf32r(b1);
                uint32_t bh0 = __float_as_uint(hb0);
                uint32_t bh1 = __float_as_uint(hb1);
                uint32_t bl0 = __float_as_uint(tf32r(b0 - hb0));
                uint32_t bl1 = __float_as_uint(tf32r(b1 - hb1));
#pragma unroll
                for (int mt = 0; mt < 2; mt++) {
                    MMA_TF32(acc[mt][nt], ah[mt], bh0, bh1);
                    MMA_TF32(acc[mt][nt], ah[mt], bl0, bl1);
                    MMA_TF32(acc[mt][nt], al[mt], bh0, bh1);
                }
            }
        }
        __syncthreads();
    }
}

template <int BN>
__global__ void __launch_bounds__(256) gemm_mma(
    const float* __restrict__ A, const float* __restrict__ W,
    const float* __restrict__ bias, float* __restrict__ C,
    int M, int N, int K)
{
    constexpr int NTW = BN / 16;
    extern __shared__ float smf[];
    const int tid = threadIdx.x;
    const int wid = tid >> 5, lane = tid & 31;
    const int g = lane >> 2, tg = lane & 3;
    const int wm = (wid & 3) * 32;
    const int wn = (wid >> 2) * (BN / 2);
    const int m0 = blockIdx.x * 128;
    const int n0 = blockIdx.y * BN;

    float acc[2][NTW][4];
#pragma unroll
    for (int mt = 0; mt < 2; mt++)
#pragma unroll
        for (int nt = 0; nt < NTW; nt++)
#pragma unroll
            for (int j = 0; j < 4; j++) acc[mt][nt][j] = 0.f;

    mma_mainloop<BN, NTW>(A, W, K, m0, n0, smf, smem_u32(smf),
                          tid, wid, lane, g, tg, wm, wn, acc);

#pragma unroll
    for (int mt = 0; mt < 2; mt++) {
#pragma unroll
        for (int nt = 0; nt < NTW; nt++) {
            int row = m0 + wm + mt * 16 + g;
            int col = n0 + wn + nt * 8 + 2 * tg;
            float b0 = __ldg(&bias[col]);
            float b1 = __ldg(&bias[col + 1]);
            float2 o0, o1;
            o0.x = fmaxf(acc[mt][nt][0] + b0, 0.f);
            o0.y = fmaxf(acc[mt][nt][1] + b1, 0.f);
            o1.x = fmaxf(acc[mt][nt][2] + b0, 0.f);
            o1.y = fmaxf(acc[mt][nt][3] + b1, 0.f);
            *reinterpret_cast<float2*>(C + (size_t)row * N + col) = o0;
            *reinterpret_cast<float2*>(C + (size_t)(row + 8) * N + col) = o1;
        }
    }
}

template <int BN, int PR>
__global__ void __launch_bounds__(256) gemm_mma_pool(
    const float* __restrict__ A, const float* __restrict__ W,
    const float* __restrict__ bias, float* __restrict__ dst,
    int M, int N, int K)
{
    constexpr int NTW = BN / 16;
    extern __shared__ float smf[];
    __shared__ float sbuf[4][BN];
    const int tid = threadIdx.x;
    const int wid = tid >> 5, lane = tid & 31;
    const int g = lane >> 2, tg = lane & 3;
    const int wm = (wid & 3) * 32;
    const int wn = (wid >> 2) * (BN / 2);
    const int m0 = blockIdx.x * 128;
    const int n0 = blockIdx.y * BN;

    float acc[2][NTW][4];
#pragma unroll
    for (int mt = 0; mt < 2; mt++)
#pragma unroll
        for (int nt = 0; nt < NTW; nt++)
#pragma unroll
            for (int j = 0; j < 4; j++) acc[mt][nt][j] = 0.f;

    mma_mainloop<BN, NTW>(A, W, K, m0, n0, smf, smem_u32(smf),
                          tid, wid, lane, g, tg, wm, wn, acc);

#pragma unroll
    for (int nt = 0; nt < NTW; nt++) {
        float v0 = fmaxf(fmaxf(acc[0][nt][0], acc[0][nt][2]),
                         fmaxf(acc[1][nt][0], acc[1][nt][2]));
        float v1 = fmaxf(fmaxf(acc[0][nt][1], acc[0][nt][3]),
                         fmaxf(acc[1][nt][1], acc[1][nt][3]));
#pragma unroll
        for (int off = 4; off < 32; off <<= 1) {
            v0 = fmaxf(v0, __shfl_xor_sync(0xffffffffu, v0, off));
            v1 = fmaxf(v1, __shfl_xor_sync(0xffffffffu, v1, off));
        }
        if (g == 0) {
            int lcol = wn + nt * 8 + 2 * tg;
            if (PR == 32) {
                int center = blockIdx.x * 4 + (wid & 3);
                int col = n0 + lcol;
                dst[(size_t)center * N + col] =
                    fmaxf(v0 + __ldg(&bias[col]), 0.f);
                dst[(size_t)center * N + col + 1] =
                    fmaxf(v1 + __ldg(&bias[col + 1]), 0.f);
            } else {
                sbuf[wid & 3][lcol] = v0;
                sbuf[wid & 3][lcol + 1] = v1;
            }
        }
    }
    if (PR == 128) {
        __syncthreads();
        if (tid < BN) {
            float m = fmaxf(fmaxf(sbuf[0][tid], sbuf[1][tid]),
                            fmaxf(sbuf[2][tid], sbuf[3][tid]));
            int col = n0 + tid;
            dst[(size_t)blockIdx.x * N + col] =
                fmaxf(m + __ldg(&bias[col]), 0.f);
        }
    }
}

// ---------------------------------------------------------------------------
static void run_mma(const float* A, const float* W, const float* bias,
                    float* C, int M, int N, int K)
{
    if (N % 128 == 0) {
        const int smem = 2 * (128 + 128) * 36 * 4;
        cudaFuncSetAttribute(gemm_mma<128>,
                             cudaFuncAttributeMaxDynamicSharedMemorySize, smem);
        dim3 g(M / 128, N / 128);
        gemm_mma<128><<<g, 256, smem>>>(A, W, bias, C, M, N, K);
    } else {
        const int smem = 2 * (128 + 64) * 36 * 4;
        cudaFuncSetAttribute(gemm_mma<64>,
                             cudaFuncAttributeMaxDynamicSharedMemorySize, smem);
        dim3 g(M / 128, N / 64);
        gemm_mma<64><<<g, 256, smem>>>(A, W, bias, C, M, N, K);
    }
}

template <int PR>
static void run_mma_pool(const float* A, const float* W, const float* bias,
                         float* dst, int M, int N, int K)
{
    const int smem = 2 * (128 + 128) * 36 * 4;
    cudaFuncSetAttribute(gemm_mma_pool<128, PR>,
                         cudaFuncAttributeMaxDynamicSharedMemorySize, smem);
    dim3 g(M / 128, N / 128);
    gemm_mma_pool<128, PR><<<g, 256, smem>>>(A, W, bias, dst, M, N, K);
}

extern "C" void kernel_launch(void* const* d_in, const int* in_sizes, int n_in,
                              void* d_out, int out_size)
{
    (void)in_sizes; (void)n_in; (void)out_size;
    const float* data = (const float*)d_in[0];
    const float *w[9], *bi[9];
    for (int i = 0; i < 9; i++) {
        w[i]  = (const float*)d_in[1 + 2 * i];
        bi[i] = (const float*)d_in[2 + 2 * i];
    }

    float *scr0, *scr1, *f1, *f2, *nx1, *nx2, *x3, *w2p, *w3p;
    int *g1, *g2;
    cudaGetSymbolAddress((void**)&scr0, g_scr0);
    cudaGetSymbolAddress((void**)&scr1, g_scr1);
    cudaGetSymbolAddress((void**)&f1, g_f1);
    cudaGetSymbolAddress((void**)&f2, g_f2);
    cudaGetSymbolAddress((void**)&nx1, g_nx1);
    cudaGetSymbolAddress((void**)&nx2, g_nx2);
    cudaGetSymbolAddress((void**)&g1, g_g1);
    cudaGetSymbolAddress((void**)&g2, g_g2);
    cudaGetSymbolAddress((void**)&x3, g_x3);
    cudaGetSymbolAddress((void**)&w2p, g_w2p);
    cudaGetSymbolAddress((void**)&w3p, g_w3p);

    const float R2a = (float)(0.2 * 0.2);
    const float R2b = (float)(0.4 * 0.4);

    padw_kernel<<<(128 * 160 + 255) / 256, 256>>>(w[3], w2p, 128, 131, 160);
    padw_kernel<<<(256 * 288 + 255) / 256, 256>>>(w[6], w3p, 256, 259, 288);

    // ---- Stage 1 ----
    fps_kernel<N1, S1, 512><<<BB, 512>>>(data, nx1);
    {
        const int smem = 3 * N1 * 4 + 32 * 32 * 4;   // 53248
        cudaFuncSetAttribute(ballq1_smem,
                             cudaFuncAttributeMaxDynamicSharedMemorySize, smem);
        ballq1_smem<<<BB * 8, 1024, smem>>>(data, nx1, R2a, g1);
    }
    gather1_kernel<<<(BB * S1 * NS + 255) / 256, 256>>>(data, scr1);
    {
        dim3 g((BB * S1 * NS) / 128, 1);
        gemm_bias_relu<<<g, 256>>>(scr1, w[0], bi[0], scr0, BB * S1 * NS, 64, 3, 3);
    }
    run_mma(scr0, w[1], bi[1], scr1, BB * S1 * NS, 64, 64);
    run_mma_pool<32>(scr1, w[2], bi[2], f1, BB * S1 * NS, 128, 64);

    // ---- Stage 2 ----
    fps2_ballq2<<<BB, 256>>>(nx1, nx2, R2b, g2);
    gather2_kernel<<<(BB * S2 * NS) / 4, 128>>>(scr0);
    run_mma(scr0, w2p, bi[3], scr1, BB * S2 * NS, 128, 160);
    run_mma(scr1, w[4], bi[4], scr0, BB * S2 * NS, 128, 128);
    run_mma_pool<32>(scr0, w[5], bi[5], f2, BB * S2 * NS, 256, 128);

    // ---- Stage 3 ----
    concat3_kernel<<<(BB * S2 * 288 + 255) / 256, 256>>>(x3);
    run_mma(x3, w3p, bi[6], scr0, BB * S2, 256, 288);
    run_mma(scr0, w[7], bi[7], scr1, BB * S2, 512, 256);
    run_mma_pool<128>(scr1, w[8], bi[8], (float*)d_out, BB * S2, 1024, 512);
}

// round 13
// speedup vs baseline: 1.0523x; 1.0319x over previous
#include <cuda_runtime.h>
#include <cstdint>

// ---------------------------------------------------------------------------
// PointNet++ encoder on GB300 (base sm_103 PTX: mma.sync + cp.async only).
// FPS / ball-query: exact fp32 (bitwise-match indices vs JAX ref).
// MLP: mma.sync m16n8k8 tf32, 3-term fp32 emulation, cp.async double buffer.
// Producer fusion: ballq1 emits gathered rows; K=3 layer fused into L1_1;
// stage-2 gather fused into L2_0 prefetch. Pools fused into final layers.
// ---------------------------------------------------------------------------

#define BB   32
#define N1   4096
#define S1   256
#define S2   128
#define NS   32

__device__ float g_scr0[262144 * 128];   // 134 MB
__device__ float g_scr1[262144 * 128];   // 134 MB
__device__ float g_f1[BB * S1 * 128];
__device__ float g_f2[BB * S2 * 256];
__device__ float g_nx1[BB * S1 * 3];
__device__ float g_nx2[BB * S2 * 3];
__device__ int   g_g2[BB * S2 * NS];
__device__ float g_x3[BB * S2 * 288];
__device__ float g_w2p[128 * 160];       // reordered [f128 | xyz3 | pad29]
__device__ float g_w3p[256 * 288];

__device__ __forceinline__ float tf32r(float x) {
    float r;
    asm("cvt.rna.tf32.f32 %0, %1;" : "=f"(r) : "f"(x));
    return r;
}
__device__ __forceinline__ uint32_t smem_u32(const void* p) {
    uint32_t a;
    asm("{ .reg .u64 t; cvta.to.shared.u64 t, %1; cvt.u32.u64 %0, t; }"
        : "=r"(a) : "l"(p));
    return a;
}
__device__ __forceinline__ void cp16(uint32_t dst, const void* src) {
    asm volatile("cp.async.ca.shared.global [%0], [%1], 16;"
                 :: "r"(dst), "l"(src) : "memory");
}
#define CP_COMMIT() asm volatile("cp.async.commit_group;" ::: "memory")
#define CP_WAIT0()  asm volatile("cp.async.wait_group 0;" ::: "memory")
#define CP_WAIT1()  asm volatile("cp.async.wait_group 1;" ::: "memory")
#define CP_WAIT2()  asm volatile("cp.async.wait_group 2;" ::: "memory")

#define MMA_TF32(c, a, b0, b1)                                                \
    asm volatile(                                                             \
        "mma.sync.aligned.m16n8k8.row.col.f32.tf32.tf32.f32 "                 \
        "{%0,%1,%2,%3}, {%4,%5,%6,%7}, {%8,%9}, {%0,%1,%2,%3};"               \
        : "+f"((c)[0]), "+f"((c)[1]), "+f"((c)[2]), "+f"((c)[3])              \
        : "r"((a)[0]), "r"((a)[1]), "r"((a)[2]), "r"((a)[3]),                 \
          "r"(b0), "r"(b1))

template <int ST>
__device__ __forceinline__ void frag_a_split(
    const float* s_a, int wm, int g, int ck, uint32_t ah[2][4], uint32_t al[2][4])
{
#pragma unroll
    for (int mt = 0; mt < 2; mt++) {
        int r0 = wm + mt * 16 + g;
        float a0 = s_a[r0 * ST + ck];
        float a1 = s_a[(r0 + 8) * ST + ck];
        float a2 = s_a[r0 * ST + ck + 4];
        float a3 = s_a[(r0 + 8) * ST + ck + 4];
        float h0 = tf32r(a0), h1 = tf32r(a1), h2 = tf32r(a2), h3 = tf32r(a3);
        ah[mt][0] = __float_as_uint(h0);
        ah[mt][1] = __float_as_uint(h1);
        ah[mt][2] = __float_as_uint(h2);
        ah[mt][3] = __float_as_uint(h3);
        al[mt][0] = __float_as_uint(tf32r(a0 - h0));
        al[mt][1] = __float_as_uint(tf32r(a1 - h1));
        al[mt][2] = __float_as_uint(tf32r(a2 - h2));
        al[mt][3] = __float_as_uint(tf32r(a3 - h3));
    }
}

// B-fragment split + 3-term emulated mma applied to both m-tiles.
__device__ __forceinline__ void bfrag_mma(
    const float* s_w, int STW, int n, int ck,
    const uint32_t ah[2][4], const uint32_t al[2][4],
    float* acc0, float* acc1)
{
    float b0v = s_w[n * STW + ck];
    float b1v = s_w[n * STW + ck + 4];
    float hb0 = tf32r(b0v), hb1 = tf32r(b1v);
    uint32_t bh0 = __float_as_uint(hb0);
    uint32_t bh1 = __float_as_uint(hb1);
    uint32_t bl0 = __float_as_uint(tf32r(b0v - hb0));
    uint32_t bl1 = __float_as_uint(tf32r(b1v - hb1));
    MMA_TF32(acc0, ah[0], bh0, bh1);
    MMA_TF32(acc0, ah[0], bl0, bl1);
    MMA_TF32(acc0, al[0], bh0, bh1);
    MMA_TF32(acc1, ah[1], bh0, bh1);
    MMA_TF32(acc1, ah[1], bl0, bl1);
    MMA_TF32(acc1, al[1], bh0, bh1);
}

// ---------------------------------------------------------------------------
// FPS stage 1 (bitwise exact vs reference)
// ---------------------------------------------------------------------------
template <int N, int NPTS, int THREADS>
__global__ void __launch_bounds__(THREADS) fps_kernel(
    const float* __restrict__ xyz_all, float* __restrict__ new_xyz)
{
    constexpr int PPT = N / THREADS;
    const int b = blockIdx.x;
    const int t = threadIdx.x;
    const float* xyz = xyz_all + (size_t)b * N * 3;

    float px[PPT], py[PPT], pz[PPT], md[PPT];
#pragma unroll
    for (int j = 0; j < PPT; j++) {
        int i = t + j * THREADS;
        px[j] = xyz[i * 3 + 0];
        py[j] = xyz[i * 3 + 1];
        pz[j] = xyz[i * 3 + 2];
        md[j] = 1e10f;
    }

    __shared__ unsigned long long wred[THREADS / 32];
    __shared__ int s_last;

    int last = 0;
    for (int it = 0; it < NPTS; it++) {
        float lx = __ldg(&xyz[last * 3 + 0]);
        float ly = __ldg(&xyz[last * 3 + 1]);
        float lz = __ldg(&xyz[last * 3 + 2]);
        if (t == 0) {
            float* o = new_xyz + (size_t)(b * NPTS + it) * 3;
            o[0] = lx; o[1] = ly; o[2] = lz;
        }
        unsigned long long best = 0ull;
#pragma unroll
        for (int j = 0; j < PPT; j++) {
            float dx = px[j] - lx, dy = py[j] - ly, dz = pz[j] - lz;
            float d = __fadd_rn(__fadd_rn(__fmul_rn(dx, dx), __fmul_rn(dy, dy)),
                                __fmul_rn(dz, dz));
            float m = fminf(md[j], d);
            md[j] = m;
            unsigned long long key =
                (((unsigned long long)__float_as_uint(m)) << 32) |
                (unsigned)(0xFFFFFFFFu - (unsigned)(t + j * THREADS));
            best = (key > best) ? key : best;
        }
#pragma unroll
        for (int off = 16; off > 0; off >>= 1) {
            unsigned long long o = __shfl_down_sync(0xffffffffu, best, off);
            best = (o > best) ? o : best;
        }
        if ((t & 31) == 0) wred[t >> 5] = best;
        __syncthreads();
        if (t < 32) {
            unsigned long long v = (t < THREADS / 32) ? wred[t] : 0ull;
#pragma unroll
            for (int off = 16; off > 0; off >>= 1) {
                unsigned long long o = __shfl_down_sync(0xffffffffu, v, off);
                v = (o > v) ? o : v;
            }
            if (t == 0)
                s_last = (int)(0xFFFFFFFFu - (unsigned)(v & 0xFFFFFFFFull));
        }
        __syncthreads();
        last = s_last;
    }
}

// ---------------------------------------------------------------------------
// Stage-1 ball query + gather: writes (p - ctr) rows (stride 4) directly.
// ---------------------------------------------------------------------------
__global__ void __launch_bounds__(1024) ballq1_gather(
    const float* __restrict__ xyz_all, const float* __restrict__ centers,
    float R2, float* __restrict__ xg)
{
    extern __shared__ float sm[];
    float* sx = sm;
    float* sy = sm + N1;
    float* sz = sm + 2 * N1;
    int* buf = (int*)(sm + 3 * N1);          // [32][32]

    const int b = blockIdx.x >> 3;
    const int grp = blockIdx.x & 7;
    const float* xyz = xyz_all + (size_t)b * N1 * 3;
    for (int i = threadIdx.x; i < N1; i += 1024) {
        sx[i] = xyz[i * 3 + 0];
        sy[i] = xyz[i * 3 + 1];
        sz[i] = xyz[i * 3 + 2];
    }
    __syncthreads();

    const int wid = threadIdx.x >> 5, lane = threadIdx.x & 31;
    int* mybuf = buf + wid * 32;
    const int s = grp * 32 + wid;
    const int gw = b * S1 + s;
    const float cx = centers[gw * 3 + 0];
    const float cy = centers[gw * 3 + 1];
    const float cz = centers[gw * 3 + 2];
    int cnt = 0;
    for (int base = 0; base < N1; base += 32) {
        int p = base + lane;
        float dx = sx[p] - cx;
        float dy = sy[p] - cy;
        float dz = sz[p] - cz;
        float d2 = __fadd_rn(__fadd_rn(__fmul_rn(dx, dx), __fmul_rn(dy, dy)),
                             __fmul_rn(dz, dz));
        bool pred = d2 < R2;
        unsigned mask = __ballot_sync(0xffffffffu, pred);
        if (pred) {
            int pos = cnt + __popc(mask & ((1u << lane) - 1u));
            if (pos < NS) mybuf[pos] = p;
        }
        cnt += __popc(mask);
        if (cnt >= NS) break;
    }
    __syncwarp();
    int nv = cnt < NS ? cnt : NS;
    int first = (cnt > 0) ? mybuf[0] : 0;
    int val = (lane < nv) ? mybuf[lane] : first;
    float4 o;
    o.x = sx[val] - cx;
    o.y = sy[val] - cy;
    o.z = sz[val] - cz;
    o.w = 0.f;
    *reinterpret_cast<float4*>(xg + ((size_t)gw * 32 + lane) * 4) = o;
}

// ---------------------------------------------------------------------------
// Fused FPS stage 2 + ball query 2 (one block per batch, smem-resident).
// ---------------------------------------------------------------------------
__global__ void __launch_bounds__(256) fps2_ballq2(
    const float* __restrict__ xyz_all, float* __restrict__ new_xyz,
    float R2, int* __restrict__ out)
{
    __shared__ float s_px[S1], s_py[S1], s_pz[S1];
    __shared__ float s_cx[S2], s_cy[S2], s_cz[S2];
    __shared__ unsigned long long wred[8];
    __shared__ int s_last;
    __shared__ int buf[8][32];

    const int b = blockIdx.x;
    const int t = threadIdx.x;
    const float* xyz = xyz_all + (size_t)b * S1 * 3;

    float px = xyz[t * 3 + 0];
    float py = xyz[t * 3 + 1];
    float pz = xyz[t * 3 + 2];
    s_px[t] = px; s_py[t] = py; s_pz[t] = pz;
    float md = 1e10f;

    int last = 0;
    for (int it = 0; it < S2; it++) {
        float lx = __ldg(&xyz[last * 3 + 0]);
        float ly = __ldg(&xyz[last * 3 + 1]);
        float lz = __ldg(&xyz[last * 3 + 2]);
        if (t == 0) {
            float* o = new_xyz + (size_t)(b * S2 + it) * 3;
            o[0] = lx; o[1] = ly; o[2] = lz;
            s_cx[it] = lx; s_cy[it] = ly; s_cz[it] = lz;
        }
        float dx = px - lx, dy = py - ly, dz = pz - lz;
        float d = __fadd_rn(__fadd_rn(__fmul_rn(dx, dx), __fmul_rn(dy, dy)),
                            __fmul_rn(dz, dz));
        md = fminf(md, d);
        unsigned long long best =
            (((unsigned long long)__float_as_uint(md)) << 32) |
            (unsigned)(0xFFFFFFFFu - (unsigned)t);
#pragma unroll
        for (int off = 16; off > 0; off >>= 1) {
            unsigned long long o = __shfl_down_sync(0xffffffffu, best, off);
            best = (o > best) ? o : best;
        }
        if ((t & 31) == 0) wred[t >> 5] = best;
        __syncthreads();
        if (t < 32) {
            unsigned long long v = (t < 8) ? wred[t] : 0ull;
#pragma unroll
            for (int off = 16; off > 0; off >>= 1) {
                unsigned long long o = __shfl_down_sync(0xffffffffu, v, off);
                v = (o > v) ? o : v;
            }
            if (t == 0)
                s_last = (int)(0xFFFFFFFFu - (unsigned)(v & 0xFFFFFFFFull));
        }
        __syncthreads();
        last = s_last;
    }

    const int wid = t >> 5, lane = t & 31;
    int* mybuf = buf[wid];
    for (int ci = 0; ci < 16; ci++) {
        const int s = wid * 16 + ci;
        const float cx = s_cx[s], cy = s_cy[s], cz = s_cz[s];
        int cnt = 0;
        for (int base = 0; base < S1; base += 32) {
            int p = base + lane;
            float dx = s_px[p] - cx;
            float dy = s_py[p] - cy;
            float dz = s_pz[p] - cz;
            float d2 = __fadd_rn(__fadd_rn(__fmul_rn(dx, dx), __fmul_rn(dy, dy)),
                                 __fmul_rn(dz, dz));
            bool pred = d2 < R2;
            unsigned mask = __ballot_sync(0xffffffffu, pred);
            if (pred) {
                int pos = cnt + __popc(mask & ((1u << lane) - 1u));
                if (pos < NS) mybuf[pos] = p;
            }
            cnt += __popc(mask);
            if (cnt >= NS) break;
        }
        __syncwarp();
        int nv = cnt < NS ? cnt : NS;
        int first = (cnt > 0) ? mybuf[0] : 0;
        int val = (lane < nv) ? mybuf[lane] : first;
        out[((size_t)(b * S2 + s)) * NS + lane] = val;
        __syncwarp();
    }
}

// ---------------------------------------------------------------------------
// concat3 / weight pads
// ---------------------------------------------------------------------------
__global__ void concat3_kernel(float* __restrict__ x3)
{
    int t = blockIdx.x * blockDim.x + threadIdx.x;
    if (t >= BB * S2 * 288) return;
    int r = t / 288, col = t - r * 288;
    x3[t] = (col < 3) ? g_nx2[(size_t)r * 3 + col]
                      : (col < 259 ? g_f2[(size_t)r * 256 + (col - 3)] : 0.f);
}

__global__ void padw_kernel(const float* __restrict__ w, float* __restrict__ o,
                            int n, int kin, int kout)
{
    int t = blockIdx.x * blockDim.x + threadIdx.x;
    if (t >= n * kout) return;
    int r = t / kout, c = t - r * kout;
    o[t] = (c < kin) ? w[r * kin + c] : 0.f;
}

// w2 reorder: cols [0..127]=w[3..130], [128..130]=w[0..2], rest 0
__global__ void padw2_reorder(const float* __restrict__ w, float* __restrict__ o)
{
    int t = blockIdx.x * blockDim.x + threadIdx.x;
    if (t >= 128 * 160) return;
    int r = t / 160, c = t - r * 160;
    float v = 0.f;
    if (c < 128)      v = w[r * 131 + 3 + c];
    else if (c < 131) v = w[r * 131 + (c - 128)];
    o[t] = v;
}

// ---------------------------------------------------------------------------
// L1_1 fused: A = relu(xg @ w0^T + b0) computed in-kernel (K=3 layer),
// then C = relu(A @ w1^T + b1). N=64, K=64 (2 chunks). M%128==0.
// ---------------------------------------------------------------------------
__global__ void __launch_bounds__(256) gemm_l11_fused(
    const float* __restrict__ xg,
    const float* __restrict__ w0, const float* __restrict__ b0,
    const float* __restrict__ w1, const float* __restrict__ b1,
    float* __restrict__ C)
{
    extern __shared__ float smf[];
    float* s_A = smf;                        // 2 chunks x 128*36
    float* s_W = smf + 2 * 128 * 36;         // 2 chunks x 64*36
    float* s_x = s_W + 2 * 64 * 36;          // 128*4

    const int tid = threadIdx.x;
    const int wid = tid >> 5, lane = tid & 31;
    const int g = lane >> 2, tg = lane & 3;
    const int wm = (wid & 3) * 32;
    const int wn = (wid >> 2) * 32;
    const int m0 = blockIdx.x * 128;
    const uint32_t smbase = smem_u32(smf);
    const uint32_t sxoff = (uint32_t)(2 * 128 * 36 + 2 * 64 * 36) * 4u;

    // G0: xg (128 rows x 16B)
    if (tid < 128)
        cp16(smbase + sxoff + (uint32_t)tid * 16u, xg + (size_t)(m0 + tid) * 4);
    CP_COMMIT();
    // G1, G2: W chunks
#pragma unroll
    for (int kc = 0; kc < 2; kc++) {
#pragma unroll
        for (int i = 0; i < 2; i++) {
            int seg = tid + i * 256;
            int r = seg >> 3, c16 = seg & 7;
            cp16(smbase + (uint32_t)((2 * 128 * 36 + kc * 64 * 36) + r * 36 + c16 * 4) * 4u,
                 w1 + (size_t)r * 64 + kc * 32 + c16 * 4);
        }
        CP_COMMIT();
    }

    CP_WAIT2();               // xg ready
    __syncthreads();

    // compute A = relu(xg @ w0^T + b0): identical fmaf chain to old SGEMM
    for (int idx = tid; idx < 128 * 64; idx += 256) {
        int r = idx >> 6, o = idx & 63;
        const float* xr = s_x + r * 4;
        float acc = 0.f;
        acc = fmaf(xr[0], __ldg(&w0[o * 3 + 0]), acc);
        acc = fmaf(xr[1], __ldg(&w0[o * 3 + 1]), acc);
        acc = fmaf(xr[2], __ldg(&w0[o * 3 + 2]), acc);
        s_A[(o >> 5) * 128 * 36 + r * 36 + (o & 31)] =
            fmaxf(acc + __ldg(&b0[o]), 0.f);
    }

    float acc[2][4][4];
#pragma unroll
    for (int mt = 0; mt < 2; mt++)
#pragma unroll
        for (int nt = 0; nt < 4; nt++)
#pragma unroll
            for (int j = 0; j < 4; j++) acc[mt][nt][j] = 0.f;

#pragma unroll
    for (int kc = 0; kc < 2; kc++) {
        if (kc == 0) { CP_WAIT1(); } else { CP_WAIT0(); }
        __syncthreads();
        const float* s_a = s_A + kc * 128 * 36;
        const float* s_w = s_W + kc * 64 * 36;
#pragma unroll
        for (int kk = 0; kk < 4; kk++) {
            const int ck = kk * 8 + tg;
            uint32_t ah[2][4], al[2][4];
            frag_a_split<36>(s_a, wm, g, ck, ah, al);
#pragma unroll
            for (int nt = 0; nt < 4; nt++) {
                int n = wn + nt * 8 + g;
                bfrag_mma(s_w, 36, n, ck, ah, al, acc[0][nt], acc[1][nt]);
            }
        }
        __syncthreads();
    }

    // epilogue (same as gemm_mma<64>)
#pragma unroll
    for (int mt = 0; mt < 2; mt++) {
#pragma unroll
        for (int nt = 0; nt < 4; nt++) {
            int row = m0 + wm + mt * 16 + g;
            int col = wn + nt * 8 + 2 * tg;
            float b0v = __ldg(&b1[col]);
            float b1v = __ldg(&b1[col + 1]);
            float2 o0, o1;
            o0.x = fmaxf(acc[mt][nt][0] + b0v, 0.f);
            o0.y = fmaxf(acc[mt][nt][1] + b1v, 0.f);
            o1.x = fmaxf(acc[mt][nt][2] + b0v, 0.f);
            o1.y = fmaxf(acc[mt][nt][3] + b1v, 0.f);
            *reinterpret_cast<float2*>(C + (size_t)row * 64 + col) = o0;
            *reinterpret_cast<float2*>(C + (size_t)(row + 8) * 64 + col) = o1;
        }
    }
}

// ---------------------------------------------------------------------------
// Generic mma mainloop (cp.async double-buffered), CTA tile 128 x BN, BK=32.
// ---------------------------------------------------------------------------
template <int BN, int NTW>
__device__ __forceinline__ void mma_mainloop(
    const float* __restrict__ A, const float* __restrict__ W,
    int K, int m0, int n0, float* smf, uint32_t smbase,
    int tid, int wid, int lane, int g, int tg, int wm, int wn,
    float acc[2][NTW][4])
{
    constexpr int SLOT = (128 + BN) * 36;
    const int KC = K >> 5;

    auto prefetch = [&](int kc, int s) {
        const uint32_t sb = smbase + (uint32_t)(s * SLOT) * 4u;
#pragma unroll
        for (int i = 0; i < 4; i++) {
            int seg = tid + i * 256;
            int r = seg >> 3, c16 = seg & 7;
            cp16(sb + (uint32_t)(r * 36 + c16 * 4) * 4u,
                 A + (size_t)(m0 + r) * K + kc * 32 + c16 * 4);
        }
#pragma unroll
        for (int i = 0; i < BN / 32; i++) {
            int seg = tid + i * 256;
            int r = seg >> 3, c16 = seg & 7;
            cp16(sb + (uint32_t)((128 + r) * 36 + c16 * 4) * 4u,
                 W + (size_t)(n0 + r) * K + kc * 32 + c16 * 4);
        }
    };

    prefetch(0, 0);
    CP_COMMIT();

    for (int kc = 0; kc < KC; kc++) {
        if (kc + 1 < KC) prefetch(kc + 1, (kc + 1) & 1);
        CP_COMMIT();
        CP_WAIT1();
        __syncthreads();

        const float* s_a = smf + (kc & 1) * SLOT;
        const float* s_w = s_a + 128 * 36;

#pragma unroll
        for (int kk = 0; kk < 4; kk++) {
            const int ck = kk * 8 + tg;
            uint32_t ah[2][4], al[2][4];
            frag_a_split<36>(s_a, wm, g, ck, ah, al);
#pragma unroll
            for (int nt = 0; nt < NTW; nt++) {
                int n = wn + nt * 8 + g;
                bfrag_mma(s_w, 36, n, ck, ah, al, acc[0][nt], acc[1][nt]);
            }
        }
        __syncthreads();
    }
}

template <int BN>
__global__ void __launch_bounds__(256) gemm_mma(
    const float* __restrict__ A, const float* __restrict__ W,
    const float* __restrict__ bias, float* __restrict__ C,
    int M, int N, int K)
{
    constexpr int NTW = BN / 16;
    extern __shared__ float smf[];
    const int tid = threadIdx.x;
    const int wid = tid >> 5, lane = tid & 31;
    const int g = lane >> 2, tg = lane & 3;
    const int wm = (wid & 3) * 32;
    const int wn = (wid >> 2) * (BN / 2);
    const int m0 = blockIdx.x * 128;
    const int n0 = blockIdx.y * BN;

    float acc[2][NTW][4];
#pragma unroll
    for (int mt = 0; mt < 2; mt++)
#pragma unroll
        for (int nt = 0; nt < NTW; nt++)
#pragma unroll
            for (int j = 0; j < 4; j++) acc[mt][nt][j] = 0.f;

    mma_mainloop<BN, NTW>(A, W, K, m0, n0, smf, smem_u32(smf),
                          tid, wid, lane, g, tg, wm, wn, acc);

#pragma unroll
    for (int mt = 0; mt < 2; mt++) {
#pragma unroll
        for (int nt = 0; nt < NTW; nt++) {
            int row = m0 + wm + mt * 16 + g;
            int col = n0 + wn + nt * 8 + 2 * tg;
            float b0 = __ldg(&bias[col]);
            float b1 = __ldg(&bias[col + 1]);
            float2 o0, o1;
            o0.x = fmaxf(acc[mt][nt][0] + b0, 0.f);
            o0.y = fmaxf(acc[mt][nt][1] + b1, 0.f);
            o1.x = fmaxf(acc[mt][nt][2] + b0, 0.f);
            o1.y = fmaxf(acc[mt][nt][3] + b1, 0.f);
            *reinterpret_cast<float2*>(C + (size_t)row * N + col) = o0;
            *reinterpret_cast<float2*>(C + (size_t)(row + 8) * N + col) = o1;
        }
    }
}

template <int BN, int PR>
__global__ void __launch_bounds__(256) gemm_mma_pool(
    const float* __restrict__ A, const float* __restrict__ W,
    const float* __restrict__ bias, float* __restrict__ dst,
    int M, int N, int K)
{
    constexpr int NTW = BN / 16;
    extern __shared__ float smf[];
    __shared__ float sbuf[4][BN];
    const int tid = threadIdx.x;
    const int wid = tid >> 5, lane = tid & 31;
    const int g = lane >> 2, tg = lane & 3;
    const int wm = (wid & 3) * 32;
    const int wn = (wid >> 2) * (BN / 2);
    const int m0 = blockIdx.x * 128;
    const int n0 = blockIdx.y * BN;

    float acc[2][NTW][4];
#pragma unroll
    for (int mt = 0; mt < 2; mt++)
#pragma unroll
        for (int nt = 0; nt < NTW; nt++)
#pragma unroll
            for (int j = 0; j < 4; j++) acc[mt][nt][j] = 0.f;

    mma_mainloop<BN, NTW>(A, W, K, m0, n0, smf, smem_u32(smf),
                          tid, wid, lane, g, tg, wm, wn, acc);

#pragma unroll
    for (int nt = 0; nt < NTW; nt++) {
        float v0 = fmaxf(fmaxf(acc[0][nt][0], acc[0][nt][2]),
                         fmaxf(acc[1][nt][0], acc[1][nt][2]));
        float v1 = fmaxf(fmaxf(acc[0][nt][1], acc[0][nt][3]),
                         fmaxf(acc[1][nt][1], acc[1][nt][3]));
#pragma unroll
        for (int off = 4; off < 32; off <<= 1) {
            v0 = fmaxf(v0, __shfl_xor_sync(0xffffffffu, v0, off));
            v1 = fmaxf(v1, __shfl_xor_sync(0xffffffffu, v1, off));
        }
        if (g == 0) {
            int lcol = wn + nt * 8 + 2 * tg;
            if (PR == 32) {
                int center = blockIdx.x * 4 + (wid & 3);
                int col = n0 + lcol;
                dst[(size_t)center * N + col] =
                    fmaxf(v0 + __ldg(&bias[col]), 0.f);
                dst[(size_t)center * N + col + 1] =
                    fmaxf(v1 + __ldg(&bias[col + 1]), 0.f);
            } else {
                sbuf[wid & 3][lcol] = v0;
                sbuf[wid & 3][lcol + 1] = v1;
            }
        }
    }
    if (PR == 128) {
        __syncthreads();
        if (tid < BN) {
            float m = fmaxf(fmaxf(sbuf[0][tid], sbuf[1][tid]),
                            fmaxf(sbuf[2][tid], sbuf[3][tid]));
            int col = n0 + tid;
            dst[(size_t)blockIdx.x * N + col] =
                fmaxf(m + __ldg(&bias[col]), 0.f);
        }
    }
}

// ---------------------------------------------------------------------------
// L2_0 fused: A gathered from f1 via g_g2 during prefetch; K order
// [feat 0..127 | xyz | pad] (weights reordered by padw2_reorder).
// BN=128, K=160 (5 chunks), N=128. M = 131072.
// ---------------------------------------------------------------------------
__global__ void __launch_bounds__(256) gemm_l20_fused(
    const float* __restrict__ f1, const float* __restrict__ W,
    const float* __restrict__ bias, float* __restrict__ C)
{
    constexpr int BN = 128, NTW = 8, KTOT = 160;
    constexpr int SLOT = (128 + BN) * 36;
    extern __shared__ float smf[];
    int*   sbase = (int*)(smf + 2 * SLOT);       // 128 ints
    float* sxyz  = smf + 2 * SLOT + 128;         // 128*4 floats

    const int tid = threadIdx.x;
    const int wid = tid >> 5, lane = tid & 31;
    const int g = lane >> 2, tg = lane & 3;
    const int wm = (wid & 3) * 32;
    const int wn = (wid >> 2) * 64;
    const int m0 = blockIdx.x * 128;
    const uint32_t smbase = smem_u32(smf);

    if (tid < 128) {
        int R = m0 + tid;
        int c = R >> 5;
        int b = c >> 7;
        int j = g_g2[R];
        int fj = b * S1 + j;
        sbase[tid] = fj * 128;
        sxyz[tid * 4 + 0] = g_nx1[fj * 3 + 0] - g_nx2[c * 3 + 0];
        sxyz[tid * 4 + 1] = g_nx1[fj * 3 + 1] - g_nx2[c * 3 + 1];
        sxyz[tid * 4 + 2] = g_nx1[fj * 3 + 2] - g_nx2[c * 3 + 2];
    }
    __syncthreads();

    auto prefetch = [&](int kc, int s) {
        const uint32_t sb = smbase + (uint32_t)(s * SLOT) * 4u;
        if (kc < 4) {
#pragma unroll
            for (int i = 0; i < 4; i++) {
                int seg = tid + i * 256;
                int r = seg >> 3, c16 = seg & 7;
                cp16(sb + (uint32_t)(r * 36 + c16 * 4) * 4u,
                     f1 + (size_t)sbase[r] + kc * 32 + c16 * 4);
            }
        } else {
            // xyz + pad chunk: direct stores (consumed >=1 sync later)
            float* dstA = smf + s * SLOT;
            for (int idx = tid; idx < 128 * 32; idx += 256) {
                int r = idx >> 5, col = idx & 31;
                dstA[r * 36 + col] = (col < 3) ? sxyz[r * 4 + col] : 0.f;
            }
        }
#pragma unroll
        for (int i = 0; i < 4; i++) {
            int seg = tid + i * 256;
            int r = seg >> 3, c16 = seg & 7;
            cp16(sb + (uint32_t)((128 + r) * 36 + c16 * 4) * 4u,
                 W + (size_t)r * KTOT + kc * 32 + c16 * 4);
        }
    };

    float acc[2][NTW][4];
#pragma unroll
    for (int mt = 0; mt < 2; mt++)
#pragma unroll
        for (int nt = 0; nt < NTW; nt++)
#pragma unroll
            for (int j = 0; j < 4; j++) acc[mt][nt][j] = 0.f;

    prefetch(0, 0);
    CP_COMMIT();

    for (int kc = 0; kc < 5; kc++) {
        if (kc + 1 < 5) prefetch(kc + 1, (kc + 1) & 1);
        CP_COMMIT();
        CP_WAIT1();
        __syncthreads();

        const float* s_a = smf + (kc & 1) * SLOT;
        const float* s_w = s_a + 128 * 36;

#pragma unroll
        for (int kk = 0; kk < 4; kk++) {
            const int ck = kk * 8 + tg;
            uint32_t ah[2][4], al[2][4];
            frag_a_split<36>(s_a, wm, g, ck, ah, al);
#pragma unroll
            for (int nt = 0; nt < NTW; nt++) {
                int n = wn + nt * 8 + g;
                bfrag_mma(s_w, 36, n, ck, ah, al, acc[0][nt], acc[1][nt]);
            }
        }
        __syncthreads();
    }

#pragma unroll
    for (int mt = 0; mt < 2; mt++) {
#pragma unroll
        for (int nt = 0; nt < NTW; nt++) {
            int row = m0 + wm + mt * 16 + g;
            int col = wn + nt * 8 + 2 * tg;
            float b0 = __ldg(&bias[col]);
            float b1 = __ldg(&bias[col + 1]);
            float2 o0, o1;
            o0.x = fmaxf(acc[mt][nt][0] + b0, 0.f);
            o0.y = fmaxf(acc[mt][nt][1] + b1, 0.f);
            o1.x = fmaxf(acc[mt][nt][2] + b0, 0.f);
            o1.y = fmaxf(acc[mt][nt][3] + b1, 0.f);
            *reinterpret_cast<float2*>(C + (size_t)row * 128 + col) = o0;
            *reinterpret_cast<float2*>(C + (size_t)(row + 8) * 128 + col) = o1;
        }
    }
}

// ---------------------------------------------------------------------------
static void run_mma(const float* A, const float* W, const float* bias,
                    float* C, int M, int N, int K)
{
    if (N % 128 == 0) {
        const int smem = 2 * (128 + 128) * 36 * 4;
        cudaFuncSetAttribute(gemm_mma<128>,
                             cudaFuncAttributeMaxDynamicSharedMemorySize, smem);
        dim3 g(M / 128, N / 128);
        gemm_mma<128><<<g, 256, smem>>>(A, W, bias, C, M, N, K);
    } else {
        const int smem = 2 * (128 + 64) * 36 * 4;
        cudaFuncSetAttribute(gemm_mma<64>,
                             cudaFuncAttributeMaxDynamicSharedMemorySize, smem);
        dim3 g(M / 128, N / 64);
        gemm_mma<64><<<g, 256, smem>>>(A, W, bias, C, M, N, K);
    }
}

template <int PR>
static void run_mma_pool(const float* A, const float* W, const float* bias,
                         float* dst, int M, int N, int K)
{
    const int smem = 2 * (128 + 128) * 36 * 4;
    cudaFuncSetAttribute(gemm_mma_pool<128, PR>,
                         cudaFuncAttributeMaxDynamicSharedMemorySize, smem);
    dim3 g(M / 128, N / 128);
    gemm_mma_pool<128, PR><<<g, 256, smem>>>(A, W, bias, dst, M, N, K);
}

extern "C" void kernel_launch(void* const* d_in, const int* in_sizes, int n_in,
                              void* d_out, int out_size)
{
    (void)in_sizes; (void)n_in; (void)out_size;
    const float* data = (const float*)d_in[0];
    const float *w[9], *bi[9];
    for (int i = 0; i < 9; i++) {
        w[i]  = (const float*)d_in[1 + 2 * i];
        bi[i] = (const float*)d_in[2 + 2 * i];
    }

    float *scr0, *scr1, *f1, *f2, *nx1, *nx2, *x3, *w2p, *w3p;
    int *g2;
    cudaGetSymbolAddress((void**)&scr0, g_scr0);
    cudaGetSymbolAddress((void**)&scr1, g_scr1);
    cudaGetSymbolAddress((void**)&f1, g_f1);
    cudaGetSymbolAddress((void**)&f2, g_f2);
    cudaGetSymbolAddress((void**)&nx1, g_nx1);
    cudaGetSymbolAddress((void**)&nx2, g_nx2);
    cudaGetSymbolAddress((void**)&g2, g_g2);
    cudaGetSymbolAddress((void**)&x3, g_x3);
    cudaGetSymbolAddress((void**)&w2p, g_w2p);
    cudaGetSymbolAddress((void**)&w3p, g_w3p);

    const float R2a = (float)(0.2 * 0.2);
    const float R2b = (float)(0.4 * 0.4);

    padw2_reorder<<<(128 * 160 + 255) / 256, 256>>>(w[3], w2p);
    padw_kernel<<<(256 * 288 + 255) / 256, 256>>>(w[6], w3p, 256, 259, 288);

    // ---- Stage 1 ----
    fps_kernel<N1, S1, 512><<<BB, 512>>>(data, nx1);
    {
        const int smem = 3 * N1 * 4 + 32 * 32 * 4;   // 53248
        cudaFuncSetAttribute(ballq1_gather,
                             cudaFuncAttributeMaxDynamicSharedMemorySize, smem);
        ballq1_gather<<<BB * 8, 1024, smem>>>(data, nx1, R2a, scr1);
    }
    {
        const int smem = (2 * 128 * 36 + 2 * 64 * 36 + 128 * 4) * 4;  // 57344
        cudaFuncSetAttribute(gemm_l11_fused,
                             cudaFuncAttributeMaxDynamicSharedMemorySize, smem);
        gemm_l11_fused<<<(BB * S1 * NS) / 128, 256, smem>>>(
            scr1, w[0], bi[0], w[1], bi[1], scr0);
    }
    run_mma_pool<32>(scr0, w[2], bi[2], f1, BB * S1 * NS, 128, 64);

    // ---- Stage 2 ----
    fps2_ballq2<<<BB, 256>>>(nx1, nx2, R2b, g2);
    {
        const int smem = (2 * (128 + 128) * 36 + 128 + 128 * 4) * 4;  // 76288
        cudaFuncSetAttribute(gemm_l20_fused,
                             cudaFuncAttributeMaxDynamicSharedMemorySize, smem);
        gemm_l20_fused<<<(BB * S2 * NS) / 128, 256, smem>>>(f1, w2p, bi[3], scr1);
    }
    run_mma(scr1, w[4], bi[4], scr0, BB * S2 * NS, 128, 128);
    run_mma_pool<32>(scr0, w[5], bi[5], f2, BB * S2 * NS, 256, 128);

    // ---- Stage 3 ----
    concat3_kernel<<<(BB * S2 * 288 + 255) / 256, 256>>>(x3);
    run_mma(x3, w3p, bi[6], scr0, BB * S2, 256, 288);
    run_mma(scr0, w[7], bi[7], scr1, BB * S2, 512, 256);
    run_mma_pool<128>(scr1, w[8], bi[8], (float*)d_out, BB * S2, 1024, 512);
}

// round 14
// speedup vs baseline: 1.3473x; 1.2804x over previous
#include <cuda_runtime.h>
#include <cuda_bf16.h>
#include <cstdint>

// ---------------------------------------------------------------------------
// PointNet++ encoder on GB300 (base sm_103 PTX: mma.sync + cp.async only).
// FPS / ball-query: exact fp32 (bitwise-match indices vs JAX ref).
// MLP: mma.sync m16n8k16 bf16, 3-term fp32 emulation (hi/lo bf16 split),
// cp.async double buffering. Producer fusion: ballq1 emits gathered rows;
// K=3 layer fused into L1_1; stage-2 gather fused into L2_0 prefetch.
// Pools fused into final layer of each stage.
// ---------------------------------------------------------------------------

#define BB   32
#define N1   4096
#define S1   256
#define S2   128
#define NS   32
#define ST   40     // smem row stride (floats): conflict-free float2 frags

__device__ float g_scr0[262144 * 128];   // 134 MB
__device__ float g_scr1[262144 * 128];   // 134 MB
__device__ float g_f1[BB * S1 * 128];
__device__ float g_f2[BB * S2 * 256];
__device__ float g_nx1[BB * S1 * 3];
__device__ float g_nx2[BB * S2 * 3];
__device__ int   g_g2[BB * S2 * NS];
__device__ float g_x3[BB * S2 * 288];
__device__ float g_w2p[128 * 160];       // reordered [f128 | xyz3 | pad29]
__device__ float g_w3p[256 * 288];

__device__ __forceinline__ uint32_t smem_u32(const void* p) {
    uint32_t a;
    asm("{ .reg .u64 t; cvta.to.shared.u64 t, %1; cvt.u32.u64 %0, t; }"
        : "=r"(a) : "l"(p));
    return a;
}
__device__ __forceinline__ void cp16(uint32_t dst, const void* src) {
    asm volatile("cp.async.ca.shared.global [%0], [%1], 16;"
                 :: "r"(dst), "l"(src) : "memory");
}
#define CP_COMMIT() asm volatile("cp.async.commit_group;" ::: "memory")
#define CP_WAIT0()  asm volatile("cp.async.wait_group 0;" ::: "memory")
#define CP_WAIT1()  asm volatile("cp.async.wait_group 1;" ::: "memory")
#define CP_WAIT2()  asm volatile("cp.async.wait_group 2;" ::: "memory")

#define MMA_BF16(c, a, b0, b1)                                                \
    asm volatile(                                                             \
        "mma.sync.aligned.m16n8k16.row.col.f32.bf16.bf16.f32 "                \
        "{%0,%1,%2,%3}, {%4,%5,%6,%7}, {%8,%9}, {%0,%1,%2,%3};"               \
        : "+f"((c)[0]), "+f"((c)[1]), "+f"((c)[2]), "+f"((c)[3])              \
        : "r"((a)[0]), "r"((a)[1]), "r"((a)[2]), "r"((a)[3]),                 \
          "r"(b0), "r"(b1))

// Split a float pair into packed bf16x2 hi and lo (x in low half = even k).
__device__ __forceinline__ void split_pair(float x, float y,
                                           uint32_t& hi, uint32_t& lo)
{
    __nv_bfloat162 h = __floats2bfloat162_rn(x, y);
    float hx = __bfloat162float(__low2bfloat16(h));
    float hy = __bfloat162float(__high2bfloat16(h));
    __nv_bfloat162 l = __floats2bfloat162_rn(x - hx, y - hy);
    hi = *reinterpret_cast<uint32_t*>(&h);
    lo = *reinterpret_cast<uint32_t*>(&l);
}

// A fragment (m16n8k16, 2 m-tiles) for one k16 group starting at column kb.
__device__ __forceinline__ void frag_a_bf16(
    const float* s_a, int wm, int g, int tg, int kb,
    uint32_t ah[2][4], uint32_t al[2][4])
{
#pragma unroll
    for (int mt = 0; mt < 2; mt++) {
        int r0 = wm + mt * 16 + g;
        float2 p0 = *reinterpret_cast<const float2*>(&s_a[r0 * ST + kb + 2 * tg]);
        float2 p1 = *reinterpret_cast<const float2*>(&s_a[(r0 + 8) * ST + kb + 2 * tg]);
        float2 p2 = *reinterpret_cast<const float2*>(&s_a[r0 * ST + kb + 2 * tg + 8]);
        float2 p3 = *reinterpret_cast<const float2*>(&s_a[(r0 + 8) * ST + kb + 2 * tg + 8]);
        split_pair(p0.x, p0.y, ah[mt][0], al[mt][0]);
        split_pair(p1.x, p1.y, ah[mt][1], al[mt][1]);
        split_pair(p2.x, p2.y, ah[mt][2], al[mt][2]);
        split_pair(p3.x, p3.y, ah[mt][3], al[mt][3]);
    }
}

// B fragment split + 3-term emulated mma applied to both m-tiles.
__device__ __forceinline__ void bfrag_mma_bf16(
    const float* s_w, int n, int kb, int tg,
    const uint32_t ah[2][4], const uint32_t al[2][4],
    float* acc0, float* acc1)
{
    float2 q0 = *reinterpret_cast<const float2*>(&s_w[n * ST + kb + 2 * tg]);
    float2 q1 = *reinterpret_cast<const float2*>(&s_w[n * ST + kb + 2 * tg + 8]);
    uint32_t bh0, bl0, bh1, bl1;
    split_pair(q0.x, q0.y, bh0, bl0);
    split_pair(q1.x, q1.y, bh1, bl1);
    MMA_BF16(acc0, ah[0], bh0, bh1);
    MMA_BF16(acc0, ah[0], bl0, bl1);
    MMA_BF16(acc0, al[0], bh0, bh1);
    MMA_BF16(acc1, ah[1], bh0, bh1);
    MMA_BF16(acc1, ah[1], bl0, bl1);
    MMA_BF16(acc1, al[1], bh0, bh1);
}

// ---------------------------------------------------------------------------
// FPS stage 1 (bitwise exact vs reference)
// ---------------------------------------------------------------------------
template <int N, int NPTS, int THREADS>
__global__ void __launch_bounds__(THREADS) fps_kernel(
    const float* __restrict__ xyz_all, float* __restrict__ new_xyz)
{
    constexpr int PPT = N / THREADS;
    const int b = blockIdx.x;
    const int t = threadIdx.x;
    const float* xyz = xyz_all + (size_t)b * N * 3;

    float px[PPT], py[PPT], pz[PPT], md[PPT];
#pragma unroll
    for (int j = 0; j < PPT; j++) {
        int i = t + j * THREADS;
        px[j] = xyz[i * 3 + 0];
        py[j] = xyz[i * 3 + 1];
        pz[j] = xyz[i * 3 + 2];
        md[j] = 1e10f;
    }

    __shared__ unsigned long long wred[THREADS / 32];
    __shared__ int s_last;

    int last = 0;
    for (int it = 0; it < NPTS; it++) {
        float lx = __ldg(&xyz[last * 3 + 0]);
        float ly = __ldg(&xyz[last * 3 + 1]);
        float lz = __ldg(&xyz[last * 3 + 2]);
        if (t == 0) {
            float* o = new_xyz + (size_t)(b * NPTS + it) * 3;
            o[0] = lx; o[1] = ly; o[2] = lz;
        }
        unsigned long long best = 0ull;
#pragma unroll
        for (int j = 0; j < PPT; j++) {
            float dx = px[j] - lx, dy = py[j] - ly, dz = pz[j] - lz;
            float d = __fadd_rn(__fadd_rn(__fmul_rn(dx, dx), __fmul_rn(dy, dy)),
                                __fmul_rn(dz, dz));
            float m = fminf(md[j], d);
            md[j] = m;
            unsigned long long key =
                (((unsigned long long)__float_as_uint(m)) << 32) |
                (unsigned)(0xFFFFFFFFu - (unsigned)(t + j * THREADS));
            best = (key > best) ? key : best;
        }
#pragma unroll
        for (int off = 16; off > 0; off >>= 1) {
            unsigned long long o = __shfl_down_sync(0xffffffffu, best, off);
            best = (o > best) ? o : best;
        }
        if ((t & 31) == 0) wred[t >> 5] = best;
        __syncthreads();
        if (t < 32) {
            unsigned long long v = (t < THREADS / 32) ? wred[t] : 0ull;
#pragma unroll
            for (int off = 16; off > 0; off >>= 1) {
                unsigned long long o = __shfl_down_sync(0xffffffffu, v, off);
                v = (o > v) ? o : v;
            }
            if (t == 0)
                s_last = (int)(0xFFFFFFFFu - (unsigned)(v & 0xFFFFFFFFull));
        }
        __syncthreads();
        last = s_last;
    }
}

// ---------------------------------------------------------------------------
// Stage-1 ball query + gather: writes (p - ctr) rows (stride 4) directly.
// ---------------------------------------------------------------------------
__global__ void __launch_bounds__(1024) ballq1_gather(
    const float* __restrict__ xyz_all, const float* __restrict__ centers,
    float R2, float* __restrict__ xg)
{
    extern __shared__ float sm[];
    float* sx = sm;
    float* sy = sm + N1;
    float* sz = sm + 2 * N1;
    int* buf = (int*)(sm + 3 * N1);          // [32][32]

    const int b = blockIdx.x >> 3;
    const int grp = blockIdx.x & 7;
    const float* xyz = xyz_all + (size_t)b * N1 * 3;
    for (int i = threadIdx.x; i < N1; i += 1024) {
        sx[i] = xyz[i * 3 + 0];
        sy[i] = xyz[i * 3 + 1];
        sz[i] = xyz[i * 3 + 2];
    }
    __syncthreads();

    const int wid = threadIdx.x >> 5, lane = threadIdx.x & 31;
    int* mybuf = buf + wid * 32;
    const int s = grp * 32 + wid;
    const int gw = b * S1 + s;
    const float cx = centers[gw * 3 + 0];
    const float cy = centers[gw * 3 + 1];
    const float cz = centers[gw * 3 + 2];
    int cnt = 0;
    for (int base = 0; base < N1; base += 32) {
        int p = base + lane;
        float dx = sx[p] - cx;
        float dy = sy[p] - cy;
        float dz = sz[p] - cz;
        float d2 = __fadd_rn(__fadd_rn(__fmul_rn(dx, dx), __fmul_rn(dy, dy)),
                             __fmul_rn(dz, dz));
        bool pred = d2 < R2;
        unsigned mask = __ballot_sync(0xffffffffu, pred);
        if (pred) {
            int pos = cnt + __popc(mask & ((1u << lane) - 1u));
            if (pos < NS) mybuf[pos] = p;
        }
        cnt += __popc(mask);
        if (cnt >= NS) break;
    }
    __syncwarp();
    int nv = cnt < NS ? cnt : NS;
    int first = (cnt > 0) ? mybuf[0] : 0;
    int val = (lane < nv) ? mybuf[lane] : first;
    float4 o;
    o.x = sx[val] - cx;
    o.y = sy[val] - cy;
    o.z = sz[val] - cz;
    o.w = 0.f;
    *reinterpret_cast<float4*>(xg + ((size_t)gw * 32 + lane) * 4) = o;
}

// ---------------------------------------------------------------------------
// Fused FPS stage 2 + ball query 2 (one block per batch, smem-resident).
// ---------------------------------------------------------------------------
__global__ void __launch_bounds__(256) fps2_ballq2(
    const float* __restrict__ xyz_all, float* __restrict__ new_xyz,
    float R2, int* __restrict__ out)
{
    __shared__ float s_px[S1], s_py[S1], s_pz[S1];
    __shared__ float s_cx[S2], s_cy[S2], s_cz[S2];
    __shared__ unsigned long long wred[8];
    __shared__ int s_last;
    __shared__ int buf[8][32];

    const int b = blockIdx.x;
    const int t = threadIdx.x;
    const float* xyz = xyz_all + (size_t)b * S1 * 3;

    float px = xyz[t * 3 + 0];
    float py = xyz[t * 3 + 1];
    float pz = xyz[t * 3 + 2];
    s_px[t] = px; s_py[t] = py; s_pz[t] = pz;
    float md = 1e10f;

    int last = 0;
    for (int it = 0; it < S2; it++) {
        float lx = __ldg(&xyz[last * 3 + 0]);
        float ly = __ldg(&xyz[last * 3 + 1]);
        float lz = __ldg(&xyz[last * 3 + 2]);
        if (t == 0) {
            float* o = new_xyz + (size_t)(b * S2 + it) * 3;
            o[0] = lx; o[1] = ly; o[2] = lz;
            s_cx[it] = lx; s_cy[it] = ly; s_cz[it] = lz;
        }
        float dx = px - lx, dy = py - ly, dz = pz - lz;
        float d = __fadd_rn(__fadd_rn(__fmul_rn(dx, dx), __fmul_rn(dy, dy)),
                            __fmul_rn(dz, dz));
        md = fminf(md, d);
        unsigned long long best =
            (((unsigned long long)__float_as_uint(md)) << 32) |
            (unsigned)(0xFFFFFFFFu - (unsigned)t);
#pragma unroll
        for (int off = 16; off > 0; off >>= 1) {
            unsigned long long o = __shfl_down_sync(0xffffffffu, best, off);
            best = (o > best) ? o : best;
        }
        if ((t & 31) == 0) wred[t >> 5] = best;
        __syncthreads();
        if (t < 32) {
            unsigned long long v = (t < 8) ? wred[t] : 0ull;
#pragma unroll
            for (int off = 16; off > 0; off >>= 1) {
                unsigned long long o = __shfl_down_sync(0xffffffffu, v, off);
                v = (o > v) ? o : v;
            }
            if (t == 0)
                s_last = (int)(0xFFFFFFFFu - (unsigned)(v & 0xFFFFFFFFull));
        }
        __syncthreads();
        last = s_last;
    }

    const int wid = t >> 5, lane = t & 31;
    int* mybuf = buf[wid];
    for (int ci = 0; ci < 16; ci++) {
        const int s = wid * 16 + ci;
        const float cx = s_cx[s], cy = s_cy[s], cz = s_cz[s];
        int cnt = 0;
        for (int base = 0; base < S1; base += 32) {
            int p = base + lane;
            float dx = s_px[p] - cx;
            float dy = s_py[p] - cy;
            float dz = s_pz[p] - cz;
            float d2 = __fadd_rn(__fadd_rn(__fmul_rn(dx, dx), __fmul_rn(dy, dy)),
                                 __fmul_rn(dz, dz));
            bool pred = d2 < R2;
            unsigned mask = __ballot_sync(0xffffffffu, pred);
            if (pred) {
                int pos = cnt + __popc(mask & ((1u << lane) - 1u));
                if (pos < NS) mybuf[pos] = p;
            }
            cnt += __popc(mask);
            if (cnt >= NS) break;
        }
        __syncwarp();
        int nv = cnt < NS ? cnt : NS;
        int first = (cnt > 0) ? mybuf[0] : 0;
        int val = (lane < nv) ? mybuf[lane] : first;
        out[((size_t)(b * S2 + s)) * NS + lane] = val;
        __syncwarp();
    }
}

// ---------------------------------------------------------------------------
// concat3 / weight pads
// ---------------------------------------------------------------------------
__global__ void concat3_kernel(float* __restrict__ x3)
{
    int t = blockIdx.x * blockDim.x + threadIdx.x;
    if (t >= BB * S2 * 288) return;
    int r = t / 288, col = t - r * 288;
    x3[t] = (col < 3) ? g_nx2[(size_t)r * 3 + col]
                      : (col < 259 ? g_f2[(size_t)r * 256 + (col - 3)] : 0.f);
}

__global__ void padw_kernel(const float* __restrict__ w, float* __restrict__ o,
                            int n, int kin, int kout)
{
    int t = blockIdx.x * blockDim.x + threadIdx.x;
    if (t >= n * kout) return;
    int r = t / kout, c = t - r * kout;
    o[t] = (c < kin) ? w[r * kin + c] : 0.f;
}

// w2 reorder: cols [0..127]=w[3..130], [128..130]=w[0..2], rest 0
__global__ void padw2_reorder(const float* __restrict__ w, float* __restrict__ o)
{
    int t = blockIdx.x * blockDim.x + threadIdx.x;
    if (t >= 128 * 160) return;
    int r = t / 160, c = t - r * 160;
    float v = 0.f;
    if (c < 128)      v = w[r * 131 + 3 + c];
    else if (c < 131) v = w[r * 131 + (c - 128)];
    o[t] = v;
}

// ---------------------------------------------------------------------------
// L1_1 fused: A = relu(xg @ w0^T + b0) computed in-kernel (K=3 layer),
// then C = relu(A @ w1^T + b1). N=64, K=64 (2 chunks). M%128==0.
// ---------------------------------------------------------------------------
__global__ void __launch_bounds__(256) gemm_l11_fused(
    const float* __restrict__ xg,
    const float* __restrict__ w0, const float* __restrict__ b0,
    const float* __restrict__ w1, const float* __restrict__ b1,
    float* __restrict__ C)
{
    extern __shared__ float smf[];
    float* s_A = smf;                        // 2 chunks x 128*ST
    float* s_W = smf + 2 * 128 * ST;         // 2 chunks x 64*ST
    float* s_x = s_W + 2 * 64 * ST;          // 128*4

    const int tid = threadIdx.x;
    const int wid = tid >> 5, lane = tid & 31;
    const int g = lane >> 2, tg = lane & 3;
    const int wm = (wid & 3) * 32;
    const int wn = (wid >> 2) * 32;
    const int m0 = blockIdx.x * 128;
    const uint32_t smbase = smem_u32(smf);
    const uint32_t sxoff = (uint32_t)(2 * 128 * ST + 2 * 64 * ST) * 4u;

    // G0: xg (128 rows x 16B)
    if (tid < 128)
        cp16(smbase + sxoff + (uint32_t)tid * 16u, xg + (size_t)(m0 + tid) * 4);
    CP_COMMIT();
    // G1, G2: W chunks
#pragma unroll
    for (int kc = 0; kc < 2; kc++) {
#pragma unroll
        for (int i = 0; i < 2; i++) {
            int seg = tid + i * 256;
            int r = seg >> 3, c16 = seg & 7;
            cp16(smbase + (uint32_t)((2 * 128 * ST + kc * 64 * ST) + r * ST + c16 * 4) * 4u,
                 w1 + (size_t)r * 64 + kc * 32 + c16 * 4);
        }
        CP_COMMIT();
    }

    CP_WAIT2();               // xg ready
    __syncthreads();

    // compute A = relu(xg @ w0^T + b0): identical fmaf chain as before
    for (int idx = tid; idx < 128 * 64; idx += 256) {
        int r = idx >> 6, o = idx & 63;
        const float* xr = s_x + r * 4;
        float acc = 0.f;
        acc = fmaf(xr[0], __ldg(&w0[o * 3 + 0]), acc);
        acc = fmaf(xr[1], __ldg(&w0[o * 3 + 1]), acc);
        acc = fmaf(xr[2], __ldg(&w0[o * 3 + 2]), acc);
        s_A[(o >> 5) * 128 * ST + r * ST + (o & 31)] =
            fmaxf(acc + __ldg(&b0[o]), 0.f);
    }

    float acc[2][4][4];
#pragma unroll
    for (int mt = 0; mt < 2; mt++)
#pragma unroll
        for (int nt = 0; nt < 4; nt++)
#pragma unroll
            for (int j = 0; j < 4; j++) acc[mt][nt][j] = 0.f;

#pragma unroll
    for (int kc = 0; kc < 2; kc++) {
        if (kc == 0) { CP_WAIT1(); } else { CP_WAIT0(); }
        __syncthreads();
        const float* s_a = s_A + kc * 128 * ST;
        const float* s_w = s_W + kc * 64 * ST;
#pragma unroll
        for (int grp = 0; grp < 2; grp++) {
            const int kb = grp * 16;
            uint32_t ah[2][4], al[2][4];
            frag_a_bf16(s_a, wm, g, tg, kb, ah, al);
#pragma unroll
            for (int nt = 0; nt < 4; nt++) {
                int n = wn + nt * 8 + g;
                bfrag_mma_bf16(s_w, n, kb, tg, ah, al, acc[0][nt], acc[1][nt]);
            }
        }
        __syncthreads();
    }

    // epilogue
#pragma unroll
    for (int mt = 0; mt < 2; mt++) {
#pragma unroll
        for (int nt = 0; nt < 4; nt++) {
            int row = m0 + wm + mt * 16 + g;
            int col = wn + nt * 8 + 2 * tg;
            float b0v = __ldg(&b1[col]);
            float b1v = __ldg(&b1[col + 1]);
            float2 o0, o1;
            o0.x = fmaxf(acc[mt][nt][0] + b0v, 0.f);
            o0.y = fmaxf(acc[mt][nt][1] + b1v, 0.f);
            o1.x = fmaxf(acc[mt][nt][2] + b0v, 0.f);
            o1.y = fmaxf(acc[mt][nt][3] + b1v, 0.f);
            *reinterpret_cast<float2*>(C + (size_t)row * 64 + col) = o0;
            *reinterpret_cast<float2*>(C + (size_t)(row + 8) * 64 + col) = o1;
        }
    }
}

// ---------------------------------------------------------------------------
// Generic mma mainloop (cp.async double-buffered), CTA tile 128 x BN, BK=32.
// ---------------------------------------------------------------------------
template <int BN, int NTW>
__device__ __forceinline__ void mma_mainloop(
    const float* __restrict__ A, const float* __restrict__ W,
    int K, int m0, int n0, float* smf, uint32_t smbase,
    int tid, int wid, int lane, int g, int tg, int wm, int wn,
    float acc[2][NTW][4])
{
    constexpr int SLOT = (128 + BN) * ST;
    const int KC = K >> 5;

    auto prefetch = [&](int kc, int s) {
        const uint32_t sb = smbase + (uint32_t)(s * SLOT) * 4u;
#pragma unroll
        for (int i = 0; i < 4; i++) {
            int seg = tid + i * 256;
            int r = seg >> 3, c16 = seg & 7;
            cp16(sb + (uint32_t)(r * ST + c16 * 4) * 4u,
                 A + (size_t)(m0 + r) * K + kc * 32 + c16 * 4);
        }
#pragma unroll
        for (int i = 0; i < BN / 32; i++) {
            int seg = tid + i * 256;
            int r = seg >> 3, c16 = seg & 7;
            cp16(sb + (uint32_t)((128 + r) * ST + c16 * 4) * 4u,
                 W + (size_t)(n0 + r) * K + kc * 32 + c16 * 4);
        }
    };

    prefetch(0, 0);
    CP_COMMIT();

    for (int kc = 0; kc < KC; kc++) {
        if (kc + 1 < KC) prefetch(kc + 1, (kc + 1) & 1);
        CP_COMMIT();
        CP_WAIT1();
        __syncthreads();

        const float* s_a = smf + (kc & 1) * SLOT;
        const float* s_w = s_a + 128 * ST;

#pragma unroll
        for (int grp = 0; grp < 2; grp++) {
            const int kb = grp * 16;
            uint32_t ah[2][4], al[2][4];
            frag_a_bf16(s_a, wm, g, tg, kb, ah, al);
#pragma unroll
            for (int nt = 0; nt < NTW; nt++) {
                int n = wn + nt * 8 + g;
                bfrag_mma_bf16(s_w, n, kb, tg, ah, al, acc[0][nt], acc[1][nt]);
            }
        }
        __syncthreads();
    }
}

template <int BN>
__global__ void __launch_bounds__(256) gemm_mma(
    const float* __restrict__ A, const float* __restrict__ W,
    const float* __restrict__ bias, float* __restrict__ C,
    int M, int N, int K)
{
    constexpr int NTW = BN / 16;
    extern __shared__ float smf[];
    const int tid = threadIdx.x;
    const int wid = tid >> 5, lane = tid & 31;
    const int g = lane >> 2, tg = lane & 3;
    const int wm = (wid & 3) * 32;
    const int wn = (wid >> 2) * (BN / 2);
    const int m0 = blockIdx.x * 128;
    const int n0 = blockIdx.y * BN;

    float acc[2][NTW][4];
#pragma unroll
    for (int mt = 0; mt < 2; mt++)
#pragma unroll
        for (int nt = 0; nt < NTW; nt++)
#pragma unroll
            for (int j = 0; j < 4; j++) acc[mt][nt][j] = 0.f;

    mma_mainloop<BN, NTW>(A, W, K, m0, n0, smf, smem_u32(smf),
                          tid, wid, lane, g, tg, wm, wn, acc);

#pragma unroll
    for (int mt = 0; mt < 2; mt++) {
#pragma unroll
        for (int nt = 0; nt < NTW; nt++) {
            int row = m0 + wm + mt * 16 + g;
            int col = n0 + wn + nt * 8 + 2 * tg;
            float b0 = __ldg(&bias[col]);
            float b1 = __ldg(&bias[col + 1]);
            float2 o0, o1;
            o0.x = fmaxf(acc[mt][nt][0] + b0, 0.f);
            o0.y = fmaxf(acc[mt][nt][1] + b1, 0.f);
            o1.x = fmaxf(acc[mt][nt][2] + b0, 0.f);
            o1.y = fmaxf(acc[mt][nt][3] + b1, 0.f);
            *reinterpret_cast<float2*>(C + (size_t)row * N + col) = o0;
            *reinterpret_cast<float2*>(C + (size_t)(row + 8) * N + col) = o1;
        }
    }
}

template <int BN, int PR>
__global__ void __launch_bounds__(256) gemm_mma_pool(
    const float* __restrict__ A, const float* __restrict__ W,
    const float* __restrict__ bias, float* __restrict__ dst,
    int M, int N, int K)
{
    constexpr int NTW = BN / 16;
    extern __shared__ float smf[];
    __shared__ float sbuf[4][BN];
    const int tid = threadIdx.x;
    const int wid = tid >> 5, lane = tid & 31;
    const int g = lane >> 2, tg = lane & 3;
    const int wm = (wid & 3) * 32;
    const int wn = (wid >> 2) * (BN / 2);
    const int m0 = blockIdx.x * 128;
    const int n0 = blockIdx.y * BN;

    float acc[2][NTW][4];
#pragma unroll
    for (int mt = 0; mt < 2; mt++)
#pragma unroll
        for (int nt = 0; nt < NTW; nt++)
#pragma unroll
            for (int j = 0; j < 4; j++) acc[mt][nt][j] = 0.f;

    mma_mainloop<BN, NTW>(A, W, K, m0, n0, smf, smem_u32(smf),
                          tid, wid, lane, g, tg, wm, wn, acc);

#pragma unroll
    for (int nt = 0; nt < NTW; nt++) {
        float v0 = fmaxf(fmaxf(acc[0][nt][0], acc[0][nt][2]),
                         fmaxf(acc[1][nt][0], acc[1][nt][2]));
        float v1 = fmaxf(fmaxf(acc[0][nt][1], acc[0][nt][3]),
                         fmaxf(acc[1][nt][1], acc[1][nt][3]));
#pragma unroll
        for (int off = 4; off < 32; off <<= 1) {
            v0 = fmaxf(v0, __shfl_xor_sync(0xffffffffu, v0, off));
            v1 = fmaxf(v1, __shfl_xor_sync(0xffffffffu, v1, off));
        }
        if (g == 0) {
            int lcol = wn + nt * 8 + 2 * tg;
            if (PR == 32) {
                int center = blockIdx.x * 4 + (wid & 3);
                int col = n0 + lcol;
                dst[(size_t)center * N + col] =
                    fmaxf(v0 + __ldg(&bias[col]), 0.f);
                dst[(size_t)center * N + col + 1] =
                    fmaxf(v1 + __ldg(&bias[col + 1]), 0.f);
            } else {
                sbuf[wid & 3][lcol] = v0;
                sbuf[wid & 3][lcol + 1] = v1;
            }
        }
    }
    if (PR == 128) {
        __syncthreads();
        if (tid < BN) {
            float m = fmaxf(fmaxf(sbuf[0][tid], sbuf[1][tid]),
                            fmaxf(sbuf[2][tid], sbuf[3][tid]));
            int col = n0 + tid;
            dst[(size_t)blockIdx.x * N + col] =
                fmaxf(m + __ldg(&bias[col]), 0.f);
        }
    }
}

// ---------------------------------------------------------------------------
// L2_0 fused: A gathered from f1 via g_g2 during prefetch; K order
// [feat 0..127 | xyz | pad] (weights reordered by padw2_reorder).
// BN=128, K=160 (5 chunks), N=128. M = 131072.
// ---------------------------------------------------------------------------
__global__ void __launch_bounds__(256) gemm_l20_fused(
    const float* __restrict__ f1, const float* __restrict__ W,
    const float* __restrict__ bias, float* __restrict__ C)
{
    constexpr int BN = 128, NTW = 8, KTOT = 160;
    constexpr int SLOT = (128 + BN) * ST;
    extern __shared__ float smf[];
    int*   sbase = (int*)(smf + 2 * SLOT);       // 128 ints
    float* sxyz  = smf + 2 * SLOT + 128;         // 128*4 floats

    const int tid = threadIdx.x;
    const int wid = tid >> 5, lane = tid & 31;
    const int g = lane >> 2, tg = lane & 3;
    const int wm = (wid & 3) * 32;
    const int wn = (wid >> 2) * 64;
    const int m0 = blockIdx.x * 128;
    const uint32_t smbase = smem_u32(smf);

    if (tid < 128) {
        int R = m0 + tid;
        int c = R >> 5;
        int b = c >> 7;
        int j = g_g2[R];
        int fj = b * S1 + j;
        sbase[tid] = fj * 128;
        sxyz[tid * 4 + 0] = g_nx1[fj * 3 + 0] - g_nx2[c * 3 + 0];
        sxyz[tid * 4 + 1] = g_nx1[fj * 3 + 1] - g_nx2[c * 3 + 1];
        sxyz[tid * 4 + 2] = g_nx1[fj * 3 + 2] - g_nx2[c * 3 + 2];
    }
    __syncthreads();

    auto prefetch = [&](int kc, int s) {
        const uint32_t sb = smbase + (uint32_t)(s * SLOT) * 4u;
        if (kc < 4) {
#pragma unroll
            for (int i = 0; i < 4; i++) {
                int seg = tid + i * 256;
                int r = seg >> 3, c16 = seg & 7;
                cp16(sb + (uint32_t)(r * ST + c16 * 4) * 4u,
                     f1 + (size_t)sbase[r] + kc * 32 + c16 * 4);
            }
        } else {
            float* dstA = smf + s * SLOT;
            for (int idx = tid; idx < 128 * 32; idx += 256) {
                int r = idx >> 5, col = idx & 31;
                dstA[r * ST + col] = (col < 3) ? sxyz[r * 4 + col] : 0.f;
            }
        }
#pragma unroll
        for (int i = 0; i < 4; i++) {
            int seg = tid + i * 256;
            int r = seg >> 3, c16 = seg & 7;
            cp16(sb + (uint32_t)((128 + r) * ST + c16 * 4) * 4u,
                 W + (size_t)r * KTOT + kc * 32 + c16 * 4);
        }
    };

    float acc[2][NTW][4];
#pragma unroll
    for (int mt = 0; mt < 2; mt++)
#pragma unroll
        for (int nt = 0; nt < NTW; nt++)
#pragma unroll
            for (int j = 0; j < 4; j++) acc[mt][nt][j] = 0.f;

    prefetch(0, 0);
    CP_COMMIT();

    for (int kc = 0; kc < 5; kc++) {
        if (kc + 1 < 5) prefetch(kc + 1, (kc + 1) & 1);
        CP_COMMIT();
        CP_WAIT1();
        __syncthreads();

        const float* s_a = smf + (kc & 1) * SLOT;
        const float* s_w = s_a + 128 * ST;

#pragma unroll
        for (int grp = 0; grp < 2; grp++) {
            const int kb = grp * 16;
            uint32_t ah[2][4], al[2][4];
            frag_a_bf16(s_a, wm, g, tg, kb, ah, al);
#pragma unroll
            for (int nt = 0; nt < NTW; nt++) {
                int n = wn + nt * 8 + g;
                bfrag_mma_bf16(s_w, n, kb, tg, ah, al, acc[0][nt], acc[1][nt]);
            }
        }
        __syncthreads();
    }

#pragma unroll
    for (int mt = 0; mt < 2; mt++) {
#pragma unroll
        for (int nt = 0; nt < NTW; nt++) {
            int row = m0 + wm + mt * 16 + g;
            int col = wn + nt * 8 + 2 * tg;
            float b0 = __ldg(&bias[col]);
            float b1 = __ldg(&bias[col + 1]);
            float2 o0, o1;
            o0.x = fmaxf(acc[mt][nt][0] + b0, 0.f);
            o0.y = fmaxf(acc[mt][nt][1] + b1, 0.f);
            o1.x = fmaxf(acc[mt][nt][2] + b0, 0.f);
            o1.y = fmaxf(acc[mt][nt][3] + b1, 0.f);
            *reinterpret_cast<float2*>(C + (size_t)row * 128 + col) = o0;
            *reinterpret_cast<float2*>(C + (size_t)(row + 8) * 128 + col) = o1;
        }
    }
}

// ---------------------------------------------------------------------------
static void run_mma(const float* A, const float* W, const float* bias,
                    float* C, int M, int N, int K)
{
    if (N % 128 == 0) {
        const int smem = 2 * (128 + 128) * ST * 4;    // 81920
        cudaFuncSetAttribute(gemm_mma<128>,
                             cudaFuncAttributeMaxDynamicSharedMemorySize, smem);
        dim3 g(M / 128, N / 128);
        gemm_mma<128><<<g, 256, smem>>>(A, W, bias, C, M, N, K);
    } else {
        const int smem = 2 * (128 + 64) * ST * 4;     // 61440
        cudaFuncSetAttribute(gemm_mma<64>,
                             cudaFuncAttributeMaxDynamicSharedMemorySize, smem);
        dim3 g(M / 128, N / 64);
        gemm_mma<64><<<g, 256, smem>>>(A, W, bias, C, M, N, K);
    }
}

template <int PR>
static void run_mma_pool(const float* A, const float* W, const float* bias,
                         float* dst, int M, int N, int K)
{
    const int smem = 2 * (128 + 128) * ST * 4;
    cudaFuncSetAttribute(gemm_mma_pool<128, PR>,
                         cudaFuncAttributeMaxDynamicSharedMemorySize, smem);
    dim3 g(M / 128, N / 128);
    gemm_mma_pool<128, PR><<<g, 256, smem>>>(A, W, bias, dst, M, N, K);
}

extern "C" void kernel_launch(void* const* d_in, const int* in_sizes, int n_in,
                              void* d_out, int out_size)
{
    (void)in_sizes; (void)n_in; (void)out_size;
    const float* data = (const float*)d_in[0];
    const float *w[9], *bi[9];
    for (int i = 0; i < 9; i++) {
        w[i]  = (const float*)d_in[1 + 2 * i];
        bi[i] = (const float*)d_in[2 + 2 * i];
    }

    float *scr0, *scr1, *f1, *f2, *nx1, *nx2, *x3, *w2p, *w3p;
    int *g2;
    cudaGetSymbolAddress((void**)&scr0, g_scr0);
    cudaGetSymbolAddress((void**)&scr1, g_scr1);
    cudaGetSymbolAddress((void**)&f1, g_f1);
    cudaGetSymbolAddress((void**)&f2, g_f2);
    cudaGetSymbolAddress((void**)&nx1, g_nx1);
    cudaGetSymbolAddress((void**)&nx2, g_nx2);
    cudaGetSymbolAddress((void**)&g2, g_g2);
    cudaGetSymbolAddress((void**)&x3, g_x3);
    cudaGetSymbolAddress((void**)&w2p, g_w2p);
    cudaGetSymbolAddress((void**)&w3p, g_w3p);

    const float R2a = (float)(0.2 * 0.2);
    const float R2b = (float)(0.4 * 0.4);

    padw2_reorder<<<(128 * 160 + 255) / 256, 256>>>(w[3], w2p);
    padw_kernel<<<(256 * 288 + 255) / 256, 256>>>(w[6], w3p, 256, 259, 288);

    // ---- Stage 1 ----
    fps_kernel<N1, S1, 512><<<BB, 512>>>(data, nx1);
    {
        const int smem = 3 * N1 * 4 + 32 * 32 * 4;   // 53248
        cudaFuncSetAttribute(ballq1_gather,
                             cudaFuncAttributeMaxDynamicSharedMemorySize, smem);
        ballq1_gather<<<BB * 8, 1024, smem>>>(data, nx1, R2a, scr1);
    }
    {
        const int smem = (2 * 128 * ST + 2 * 64 * ST + 128 * 4) * 4;  // 63488
        cudaFuncSetAttribute(gemm_l11_fused,
                             cudaFuncAttributeMaxDynamicSharedMemorySize, smem);
        gemm_l11_fused<<<(BB * S1 * NS) / 128, 256, smem>>>(
            scr1, w[0], bi[0], w[1], bi[1], scr0);
    }
    run_mma_pool<32>(scr0, w[2], bi[2], f1, BB * S1 * NS, 128, 64);

    // ---- Stage 2 ----
    fps2_ballq2<<<BB, 256>>>(nx1, nx2, R2b, g2);
    {
        const int smem = (2 * (128 + 128) * ST + 128 + 128 * 4) * 4;  // 84480
        cudaFuncSetAttribute(gemm_l20_fused,
                             cudaFuncAttributeMaxDynamicSharedMemorySize, smem);
        gemm_l20_fused<<<(BB * S2 * NS) / 128, 256, smem>>>(f1, w2p, bi[3], scr1);
    }
    run_mma(scr1, w[4], bi[4], scr0, BB * S2 * NS, 128, 128);
    run_mma_pool<32>(scr0, w[5], bi[5], f2, BB * S2 * NS, 256, 128);

    // ---- Stage 3 ----
    concat3_kernel<<<(BB * S2 * 288 + 255) / 256, 256>>>(x3);
    run_mma(x3, w3p, bi[6], scr0, BB * S2, 256, 288);
    run_mma(scr0, w[7], bi[7], scr1, BB * S2, 512, 256);
    run_mma_pool<128>(scr1, w[8], bi[8], (float*)d_out, BB * S2, 1024, 512);
}

// round 15
// speedup vs baseline: 1.3498x; 1.0018x over previous
#include <cuda_runtime.h>
#include <cuda_bf16.h>
#include <cstdint>

// ---------------------------------------------------------------------------
// PointNet++ encoder on GB300 (base sm_103 PTX: mma.sync + cp.async only).
// FPS / ball-query: exact fp32 (bitwise-match indices vs JAX ref).
// MLP: mma.sync m16n8k16 bf16, 3-term fp32 emulation. Generic GEMMs use
// cooperative pre-split: fp32 chunk -> smem bf16 hi/lo planes (each element
// split once), mma loop is pure LDS+mma. Producer fusion as in R13/R14.
// ---------------------------------------------------------------------------

#define BB   32
#define N1   4096
#define S1   256
#define S2   128
#define NS   32
#define ST   40     // fused-kernel smem row stride (floats)

__device__ float g_scr0[262144 * 128];   // 134 MB
__device__ float g_scr1[262144 * 128];   // 134 MB
__device__ float g_f1[BB * S1 * 128];
__device__ float g_f2[BB * S2 * 256];
__device__ float g_nx1[BB * S1 * 3];
__device__ float g_nx2[BB * S2 * 3];
__device__ int   g_g2[BB * S2 * NS];
__device__ float g_x3[BB * S2 * 288];
__device__ float g_w2p[128 * 160];       // reordered [f128 | xyz3 | pad29]
__device__ float g_w3p[256 * 288];

__device__ __forceinline__ uint32_t smem_u32(const void* p) {
    uint32_t a;
    asm("{ .reg .u64 t; cvta.to.shared.u64 t, %1; cvt.u32.u64 %0, t; }"
        : "=r"(a) : "l"(p));
    return a;
}
__device__ __forceinline__ void cp16(uint32_t dst, const void* src) {
    asm volatile("cp.async.ca.shared.global [%0], [%1], 16;"
                 :: "r"(dst), "l"(src) : "memory");
}
#define CP_COMMIT() asm volatile("cp.async.commit_group;" ::: "memory")
#define CP_WAIT0()  asm volatile("cp.async.wait_group 0;" ::: "memory")
#define CP_WAIT1()  asm volatile("cp.async.wait_group 1;" ::: "memory")
#define CP_WAIT2()  asm volatile("cp.async.wait_group 2;" ::: "memory")

#define MMA_BF16(c, a, b0, b1)                                                \
    asm volatile(                                                             \
        "mma.sync.aligned.m16n8k16.row.col.f32.bf16.bf16.f32 "                \
        "{%0,%1,%2,%3}, {%4,%5,%6,%7}, {%8,%9}, {%0,%1,%2,%3};"               \
        : "+f"((c)[0]), "+f"((c)[1]), "+f"((c)[2]), "+f"((c)[3])              \
        : "r"((a)[0]), "r"((a)[1]), "r"((a)[2]), "r"((a)[3]),                 \
          "r"(b0), "r"(b1))

// Split a float pair into packed bf16x2 hi and lo (x in low half = even k).
__device__ __forceinline__ void split_pair(float x, float y,
                                           uint32_t& hi, uint32_t& lo)
{
    __nv_bfloat162 h = __floats2bfloat162_rn(x, y);
    float hx = __bfloat162float(__low2bfloat16(h));
    float hy = __bfloat162float(__high2bfloat16(h));
    __nv_bfloat162 l = __floats2bfloat162_rn(x - hx, y - hy);
    hi = *reinterpret_cast<uint32_t*>(&h);
    lo = *reinterpret_cast<uint32_t*>(&l);
}

// ---- fused-kernel (ST=40 fp32 layout) fragment helpers (R14 path) ---------
__device__ __forceinline__ void frag_a_bf16(
    const float* s_a, int wm, int g, int tg, int kb,
    uint32_t ah[2][4], uint32_t al[2][4])
{
#pragma unroll
    for (int mt = 0; mt < 2; mt++) {
        int r0 = wm + mt * 16 + g;
        float2 p0 = *reinterpret_cast<const float2*>(&s_a[r0 * ST + kb + 2 * tg]);
        float2 p1 = *reinterpret_cast<const float2*>(&s_a[(r0 + 8) * ST + kb + 2 * tg]);
        float2 p2 = *reinterpret_cast<const float2*>(&s_a[r0 * ST + kb + 2 * tg + 8]);
        float2 p3 = *reinterpret_cast<const float2*>(&s_a[(r0 + 8) * ST + kb + 2 * tg + 8]);
        split_pair(p0.x, p0.y, ah[mt][0], al[mt][0]);
        split_pair(p1.x, p1.y, ah[mt][1], al[mt][1]);
        split_pair(p2.x, p2.y, ah[mt][2], al[mt][2]);
        split_pair(p3.x, p3.y, ah[mt][3], al[mt][3]);
    }
}
__device__ __forceinline__ void bfrag_mma_bf16(
    const float* s_w, int n, int kb, int tg,
    const uint32_t ah[2][4], const uint32_t al[2][4],
    float* acc0, float* acc1)
{
    float2 q0 = *reinterpret_cast<const float2*>(&s_w[n * ST + kb + 2 * tg]);
    float2 q1 = *reinterpret_cast<const float2*>(&s_w[n * ST + kb + 2 * tg + 8]);
    uint32_t bh0, bl0, bh1, bl1;
    split_pair(q0.x, q0.y, bh0, bl0);
    split_pair(q1.x, q1.y, bh1, bl1);
    MMA_BF16(acc0, ah[0], bh0, bh1);
    MMA_BF16(acc0, ah[0], bl0, bl1);
    MMA_BF16(acc0, al[0], bh0, bh1);
    MMA_BF16(acc1, ah[1], bh0, bh1);
    MMA_BF16(acc1, ah[1], bl0, bl1);
    MMA_BF16(acc1, al[1], bh0, bh1);
}

// ---------------------------------------------------------------------------
// FPS stage 1 (bitwise exact vs reference)
// ---------------------------------------------------------------------------
template <int N, int NPTS, int THREADS>
__global__ void __launch_bounds__(THREADS) fps_kernel(
    const float* __restrict__ xyz_all, float* __restrict__ new_xyz)
{
    constexpr int PPT = N / THREADS;
    const int b = blockIdx.x;
    const int t = threadIdx.x;
    const float* xyz = xyz_all + (size_t)b * N * 3;

    float px[PPT], py[PPT], pz[PPT], md[PPT];
#pragma unroll
    for (int j = 0; j < PPT; j++) {
        int i = t + j * THREADS;
        px[j] = xyz[i * 3 + 0];
        py[j] = xyz[i * 3 + 1];
        pz[j] = xyz[i * 3 + 2];
        md[j] = 1e10f;
    }

    __shared__ unsigned long long wred[THREADS / 32];
    __shared__ int s_last;

    int last = 0;
    for (int it = 0; it < NPTS; it++) {
        float lx = __ldg(&xyz[last * 3 + 0]);
        float ly = __ldg(&xyz[last * 3 + 1]);
        float lz = __ldg(&xyz[last * 3 + 2]);
        if (t == 0) {
            float* o = new_xyz + (size_t)(b * NPTS + it) * 3;
            o[0] = lx; o[1] = ly; o[2] = lz;
        }
        unsigned long long best = 0ull;
#pragma unroll
        for (int j = 0; j < PPT; j++) {
            float dx = px[j] - lx, dy = py[j] - ly, dz = pz[j] - lz;
            float d = __fadd_rn(__fadd_rn(__fmul_rn(dx, dx), __fmul_rn(dy, dy)),
                                __fmul_rn(dz, dz));
            float m = fminf(md[j], d);
            md[j] = m;
            unsigned long long key =
                (((unsigned long long)__float_as_uint(m)) << 32) |
                (unsigned)(0xFFFFFFFFu - (unsigned)(t + j * THREADS));
            best = (key > best) ? key : best;
        }
#pragma unroll
        for (int off = 16; off > 0; off >>= 1) {
            unsigned long long o = __shfl_down_sync(0xffffffffu, best, off);
            best = (o > best) ? o : best;
        }
        if ((t & 31) == 0) wred[t >> 5] = best;
        __syncthreads();
        if (t < 32) {
            unsigned long long v = (t < THREADS / 32) ? wred[t] : 0ull;
#pragma unroll
            for (int off = 16; off > 0; off >>= 1) {
                unsigned long long o = __shfl_down_sync(0xffffffffu, v, off);
                v = (o > v) ? o : v;
            }
            if (t == 0)
                s_last = (int)(0xFFFFFFFFu - (unsigned)(v & 0xFFFFFFFFull));
        }
        __syncthreads();
        last = s_last;
    }
}

// ---------------------------------------------------------------------------
// Stage-1 ball query + gather
// ---------------------------------------------------------------------------
__global__ void __launch_bounds__(1024) ballq1_gather(
    const float* __restrict__ xyz_all, const float* __restrict__ centers,
    float R2, float* __restrict__ xg)
{
    extern __shared__ float sm[];
    float* sx = sm;
    float* sy = sm + N1;
    float* sz = sm + 2 * N1;
    int* buf = (int*)(sm + 3 * N1);          // [32][32]

    const int b = blockIdx.x >> 3;
    const int grp = blockIdx.x & 7;
    const float* xyz = xyz_all + (size_t)b * N1 * 3;
    for (int i = threadIdx.x; i < N1; i += 1024) {
        sx[i] = xyz[i * 3 + 0];
        sy[i] = xyz[i * 3 + 1];
        sz[i] = xyz[i * 3 + 2];
    }
    __syncthreads();

    const int wid = threadIdx.x >> 5, lane = threadIdx.x & 31;
    int* mybuf = buf + wid * 32;
    const int s = grp * 32 + wid;
    const int gw = b * S1 + s;
    const float cx = centers[gw * 3 + 0];
    const float cy = centers[gw * 3 + 1];
    const float cz = centers[gw * 3 + 2];
    int cnt = 0;
    for (int base = 0; base < N1; base += 32) {
        int p = base + lane;
        float dx = sx[p] - cx;
        float dy = sy[p] - cy;
        float dz = sz[p] - cz;
        float d2 = __fadd_rn(__fadd_rn(__fmul_rn(dx, dx), __fmul_rn(dy, dy)),
                             __fmul_rn(dz, dz));
        bool pred = d2 < R2;
        unsigned mask = __ballot_sync(0xffffffffu, pred);
        if (pred) {
            int pos = cnt + __popc(mask & ((1u << lane) - 1u));
            if (pos < NS) mybuf[pos] = p;
        }
        cnt += __popc(mask);
        if (cnt >= NS) break;
    }
    __syncwarp();
    int nv = cnt < NS ? cnt : NS;
    int first = (cnt > 0) ? mybuf[0] : 0;
    int val = (lane < nv) ? mybuf[lane] : first;
    float4 o;
    o.x = sx[val] - cx;
    o.y = sy[val] - cy;
    o.z = sz[val] - cz;
    o.w = 0.f;
    *reinterpret_cast<float4*>(xg + ((size_t)gw * 32 + lane) * 4) = o;
}

// ---------------------------------------------------------------------------
// Fused FPS stage 2 + ball query 2
// ---------------------------------------------------------------------------
__global__ void __launch_bounds__(256) fps2_ballq2(
    const float* __restrict__ xyz_all, float* __restrict__ new_xyz,
    float R2, int* __restrict__ out)
{
    __shared__ float s_px[S1], s_py[S1], s_pz[S1];
    __shared__ float s_cx[S2], s_cy[S2], s_cz[S2];
    __shared__ unsigned long long wred[8];
    __shared__ int s_last;
    __shared__ int buf[8][32];

    const int b = blockIdx.x;
    const int t = threadIdx.x;
    const float* xyz = xyz_all + (size_t)b * S1 * 3;

    float px = xyz[t * 3 + 0];
    float py = xyz[t * 3 + 1];
    float pz = xyz[t * 3 + 2];
    s_px[t] = px; s_py[t] = py; s_pz[t] = pz;
    float md = 1e10f;

    int last = 0;
    for (int it = 0; it < S2; it++) {
        float lx = __ldg(&xyz[last * 3 + 0]);
        float ly = __ldg(&xyz[last * 3 + 1]);
        float lz = __ldg(&xyz[last * 3 + 2]);
        if (t == 0) {
            float* o = new_xyz + (size_t)(b * S2 + it) * 3;
            o[0] = lx; o[1] = ly; o[2] = lz;
            s_cx[it] = lx; s_cy[it] = ly; s_cz[it] = lz;
        }
        float dx = px - lx, dy = py - ly, dz = pz - lz;
        float d = __fadd_rn(__fadd_rn(__fmul_rn(dx, dx), __fmul_rn(dy, dy)),
                            __fmul_rn(dz, dz));
        md = fminf(md, d);
        unsigned long long best =
            (((unsigned long long)__float_as_uint(md)) << 32) |
            (unsigned)(0xFFFFFFFFu - (unsigned)t);
#pragma unroll
        for (int off = 16; off > 0; off >>= 1) {
            unsigned long long o = __shfl_down_sync(0xffffffffu, best, off);
            best = (o > best) ? o : best;
        }
        if ((t & 31) == 0) wred[t >> 5] = best;
        __syncthreads();
        if (t < 32) {
            unsigned long long v = (t < 8) ? wred[t] : 0ull;
#pragma unroll
            for (int off = 16; off > 0; off >>= 1) {
                unsigned long long o = __shfl_down_sync(0xffffffffu, v, off);
                v = (o > v) ? o : v;
            }
            if (t == 0)
                s_last = (int)(0xFFFFFFFFu - (unsigned)(v & 0xFFFFFFFFull));
        }
        __syncthreads();
        last = s_last;
    }

    const int wid = t >> 5, lane = t & 31;
    int* mybuf = buf[wid];
    for (int ci = 0; ci < 16; ci++) {
        const int s = wid * 16 + ci;
        const float cx = s_cx[s], cy = s_cy[s], cz = s_cz[s];
        int cnt = 0;
        for (int base = 0; base < S1; base += 32) {
            int p = base + lane;
            float dx = s_px[p] - cx;
            float dy = s_py[p] - cy;
            float dz = s_pz[p] - cz;
            float d2 = __fadd_rn(__fadd_rn(__fmul_rn(dx, dx), __fmul_rn(dy, dy)),
                                 __fmul_rn(dz, dz));
            bool pred = d2 < R2;
            unsigned mask = __ballot_sync(0xffffffffu, pred);
            if (pred) {
                int pos = cnt + __popc(mask & ((1u << lane) - 1u));
                if (pos < NS) mybuf[pos] = p;
            }
            cnt += __popc(mask);
            if (cnt >= NS) break;
        }
        __syncwarp();
        int nv = cnt < NS ? cnt : NS;
        int first = (cnt > 0) ? mybuf[0] : 0;
        int val = (lane < nv) ? mybuf[lane] : first;
        out[((size_t)(b * S2 + s)) * NS + lane] = val;
        __syncwarp();
    }
}

// ---------------------------------------------------------------------------
// concat3 / weight pads
// ---------------------------------------------------------------------------
__global__ void concat3_kernel(float* __restrict__ x3)
{
    int t = blockIdx.x * blockDim.x + threadIdx.x;
    if (t >= BB * S2 * 288) return;
    int r = t / 288, col = t - r * 288;
    x3[t] = (col < 3) ? g_nx2[(size_t)r * 3 + col]
                      : (col < 259 ? g_f2[(size_t)r * 256 + (col - 3)] : 0.f);
}

__global__ void padw_kernel(const float* __restrict__ w, float* __restrict__ o,
                            int n, int kin, int kout)
{
    int t = blockIdx.x * blockDim.x + threadIdx.x;
    if (t >= n * kout) return;
    int r = t / kout, c = t - r * kout;
    o[t] = (c < kin) ? w[r * kin + c] : 0.f;
}

__global__ void padw2_reorder(const float* __restrict__ w, float* __restrict__ o)
{
    int t = blockIdx.x * blockDim.x + threadIdx.x;
    if (t >= 128 * 160) return;
    int r = t / 160, c = t - r * 160;
    float v = 0.f;
    if (c < 128)      v = w[r * 131 + 3 + c];
    else if (c < 131) v = w[r * 131 + (c - 128)];
    o[t] = v;
}

// ---------------------------------------------------------------------------
// L1_1 fused (R14 path, unchanged)
// ---------------------------------------------------------------------------
__global__ void __launch_bounds__(256) gemm_l11_fused(
    const float* __restrict__ xg,
    const float* __restrict__ w0, const float* __restrict__ b0,
    const float* __restrict__ w1, const float* __restrict__ b1,
    float* __restrict__ C)
{
    extern __shared__ float smf[];
    float* s_A = smf;
    float* s_W = smf + 2 * 128 * ST;
    float* s_x = s_W + 2 * 64 * ST;

    const int tid = threadIdx.x;
    const int wid = tid >> 5, lane = tid & 31;
    const int g = lane >> 2, tg = lane & 3;
    const int wm = (wid & 3) * 32;
    const int wn = (wid >> 2) * 32;
    const int m0 = blockIdx.x * 128;
    const uint32_t smbase = smem_u32(smf);
    const uint32_t sxoff = (uint32_t)(2 * 128 * ST + 2 * 64 * ST) * 4u;

    if (tid < 128)
        cp16(smbase + sxoff + (uint32_t)tid * 16u, xg + (size_t)(m0 + tid) * 4);
    CP_COMMIT();
#pragma unroll
    for (int kc = 0; kc < 2; kc++) {
#pragma unroll
        for (int i = 0; i < 2; i++) {
            int seg = tid + i * 256;
            int r = seg >> 3, c16 = seg & 7;
            cp16(smbase + (uint32_t)((2 * 128 * ST + kc * 64 * ST) + r * ST + c16 * 4) * 4u,
                 w1 + (size_t)r * 64 + kc * 32 + c16 * 4);
        }
        CP_COMMIT();
    }

    CP_WAIT2();
    __syncthreads();

    for (int idx = tid; idx < 128 * 64; idx += 256) {
        int r = idx >> 6, o = idx & 63;
        const float* xr = s_x + r * 4;
        float acc = 0.f;
        acc = fmaf(xr[0], __ldg(&w0[o * 3 + 0]), acc);
        acc = fmaf(xr[1], __ldg(&w0[o * 3 + 1]), acc);
        acc = fmaf(xr[2], __ldg(&w0[o * 3 + 2]), acc);
        s_A[(o >> 5) * 128 * ST + r * ST + (o & 31)] =
            fmaxf(acc + __ldg(&b0[o]), 0.f);
    }

    float acc[2][4][4];
#pragma unroll
    for (int mt = 0; mt < 2; mt++)
#pragma unroll
        for (int nt = 0; nt < 4; nt++)
#pragma unroll
            for (int j = 0; j < 4; j++) acc[mt][nt][j] = 0.f;

#pragma unroll
    for (int kc = 0; kc < 2; kc++) {
        if (kc == 0) { CP_WAIT1(); } else { CP_WAIT0(); }
        __syncthreads();
        const float* s_a = s_A + kc * 128 * ST;
        const float* s_w = s_W + kc * 64 * ST;
#pragma unroll
        for (int grp = 0; grp < 2; grp++) {
            const int kb = grp * 16;
            uint32_t ah[2][4], al[2][4];
            frag_a_bf16(s_a, wm, g, tg, kb, ah, al);
#pragma unroll
            for (int nt = 0; nt < 4; nt++) {
                int n = wn + nt * 8 + g;
                bfrag_mma_bf16(s_w, n, kb, tg, ah, al, acc[0][nt], acc[1][nt]);
            }
        }
        __syncthreads();
    }

#pragma unroll
    for (int mt = 0; mt < 2; mt++) {
#pragma unroll
        for (int nt = 0; nt < 4; nt++) {
            int row = m0 + wm + mt * 16 + g;
            int col = wn + nt * 8 + 2 * tg;
            float b0v = __ldg(&b1[col]);
            float b1v = __ldg(&b1[col + 1]);
            float2 o0, o1;
            o0.x = fmaxf(acc[mt][nt][0] + b0v, 0.f);
            o0.y = fmaxf(acc[mt][nt][1] + b1v, 0.f);
            o1.x = fmaxf(acc[mt][nt][2] + b0v, 0.f);
            o1.y = fmaxf(acc[mt][nt][3] + b1v, 0.f);
            *reinterpret_cast<float2*>(C + (size_t)row * 64 + col) = o0;
            *reinterpret_cast<float2*>(C + (size_t)(row + 8) * 64 + col) = o1;
        }
    }
}

// ---------------------------------------------------------------------------
// v2 mainloop: fp32 staged (stride 32, double-buffered) -> cooperative split
// into bf16 hi/lo planes (u32 stride 20, conflict-free) -> pure LDS+mma.
// ---------------------------------------------------------------------------
template <int BN, int NTW>
__device__ __forceinline__ void mma_mainloop2(
    const float* __restrict__ A, const float* __restrict__ W,
    int K, int m0, int n0, float* smf, uint32_t smbase,
    int tid, int g, int tg, int wm, int wn,
    float acc[2][NTW][4])
{
    constexpr int ROWS = 128 + BN;
    constexpr int SLOTF = ROWS * 32;           // floats per fp32 slot
    constexpr int PW = 20;                     // plane stride (u32 words)
    uint32_t* hiP = (uint32_t*)(smf + 2 * SLOTF);
    uint32_t* loP = hiP + ROWS * PW;
    const int KC = K >> 5;

    auto prefetch = [&](int kc, int s) {
        const uint32_t sb = smbase + (uint32_t)(s * SLOTF) * 4u;
#pragma unroll
        for (int i = 0; i < 4; i++) {
            int seg = tid + i * 256;
            int r = seg >> 3, c16 = seg & 7;
            cp16(sb + (uint32_t)(r * 32 + c16 * 4) * 4u,
                 A + (size_t)(m0 + r) * K + kc * 32 + c16 * 4);
        }
#pragma unroll
        for (int i = 0; i < BN / 32; i++) {
            int seg = tid + i * 256;
            int r = seg >> 3, c16 = seg & 7;
            cp16(sb + (uint32_t)((128 + r) * 32 + c16 * 4) * 4u,
                 W + (size_t)(n0 + r) * K + kc * 32 + c16 * 4);
        }
    };

    prefetch(0, 0);
    CP_COMMIT();

    for (int kc = 0; kc < KC; kc++) {
        if (kc + 1 < KC) prefetch(kc + 1, (kc + 1) & 1);
        CP_COMMIT();
        CP_WAIT1();
        __syncthreads();

        const float* s_f = smf + (kc & 1) * SLOTF;

        // cooperative split: each of ROWS*16 words exactly once
#pragma unroll
        for (int i = 0; i < ROWS * 16 / 256; i++) {
            int idx = tid + i * 256;
            int r = idx >> 4, w = idx & 15;
            float2 v = *reinterpret_cast<const float2*>(&s_f[r * 32 + 2 * w]);
            uint32_t h, l;
            split_pair(v.x, v.y, h, l);
            hiP[r * PW + w] = h;
            loP[r * PW + w] = l;
        }
        __syncthreads();

#pragma unroll
        for (int grp = 0; grp < 2; grp++) {
            const int wb = grp * 8;
            uint32_t ah[2][4], al[2][4];
#pragma unroll
            for (int mt = 0; mt < 2; mt++) {
                int r0 = wm + mt * 16 + g;
                ah[mt][0] = hiP[r0 * PW + wb + tg];
                ah[mt][1] = hiP[(r0 + 8) * PW + wb + tg];
                ah[mt][2] = hiP[r0 * PW + wb + tg + 4];
                ah[mt][3] = hiP[(r0 + 8) * PW + wb + tg + 4];
                al[mt][0] = loP[r0 * PW + wb + tg];
                al[mt][1] = loP[(r0 + 8) * PW + wb + tg];
                al[mt][2] = loP[r0 * PW + wb + tg + 4];
                al[mt][3] = loP[(r0 + 8) * PW + wb + tg + 4];
            }
#pragma unroll
            for (int nt = 0; nt < NTW; nt++) {
                int nb = (128 + wn + nt * 8 + g) * PW;
                uint32_t bh0 = hiP[nb + wb + tg];
                uint32_t bh1 = hiP[nb + wb + tg + 4];
                uint32_t bl0 = loP[nb + wb + tg];
                uint32_t bl1 = loP[nb + wb + tg + 4];
                MMA_BF16(acc[0][nt], ah[0], bh0, bh1);
                MMA_BF16(acc[0][nt], ah[0], bl0, bl1);
                MMA_BF16(acc[0][nt], al[0], bh0, bh1);
                MMA_BF16(acc[1][nt], ah[1], bh0, bh1);
                MMA_BF16(acc[1][nt], ah[1], bl0, bl1);
                MMA_BF16(acc[1][nt], al[1], bh0, bh1);
            }
        }
        __syncthreads();
    }
}

template <int BN>
__global__ void __launch_bounds__(256) gemm_mma(
    const float* __restrict__ A, const float* __restrict__ W,
    const float* __restrict__ bias, float* __restrict__ C,
    int M, int N, int K)
{
    constexpr int NTW = BN / 16;
    extern __shared__ float smf[];
    const int tid = threadIdx.x;
    const int wid = tid >> 5, lane = tid & 31;
    const int g = lane >> 2, tg = lane & 3;
    const int wm = (wid & 3) * 32;
    const int wn = (wid >> 2) * (BN / 2);
    const int m0 = blockIdx.x * 128;
    const int n0 = blockIdx.y * BN;

    float acc[2][NTW][4];
#pragma unroll
    for (int mt = 0; mt < 2; mt++)
#pragma unroll
        for (int nt = 0; nt < NTW; nt++)
#pragma unroll
            for (int j = 0; j < 4; j++) acc[mt][nt][j] = 0.f;

    mma_mainloop2<BN, NTW>(A, W, K, m0, n0, smf, smem_u32(smf),
                           tid, g, tg, wm, wn, acc);

#pragma unroll
    for (int mt = 0; mt < 2; mt++) {
#pragma unroll
        for (int nt = 0; nt < NTW; nt++) {
            int row = m0 + wm + mt * 16 + g;
            int col = n0 + wn + nt * 8 + 2 * tg;
            float b0 = __ldg(&bias[col]);
            float b1 = __ldg(&bias[col + 1]);
            float2 o0, o1;
            o0.x = fmaxf(acc[mt][nt][0] + b0, 0.f);
            o0.y = fmaxf(acc[mt][nt][1] + b1, 0.f);
            o1.x = fmaxf(acc[mt][nt][2] + b0, 0.f);
            o1.y = fmaxf(acc[mt][nt][3] + b1, 0.f);
            *reinterpret_cast<float2*>(C + (size_t)row * N + col) = o0;
            *reinterpret_cast<float2*>(C + (size_t)(row + 8) * N + col) = o1;
        }
    }
}

template <int BN, int PR>
__global__ void __launch_bounds__(256) gemm_mma_pool(
    const float* __restrict__ A, const float* __restrict__ W,
    const float* __restrict__ bias, float* __restrict__ dst,
    int M, int N, int K)
{
    constexpr int NTW = BN / 16;
    extern __shared__ float smf[];
    __shared__ float sbuf[4][BN];
    const int tid = threadIdx.x;
    const int wid = tid >> 5, lane = tid & 31;
    const int g = lane >> 2, tg = lane & 3;
    const int wm = (wid & 3) * 32;
    const int wn = (wid >> 2) * (BN / 2);
    const int m0 = blockIdx.x * 128;
    const int n0 = blockIdx.y * BN;

    float acc[2][NTW][4];
#pragma unroll
    for (int mt = 0; mt < 2; mt++)
#pragma unroll
        for (int nt = 0; nt < NTW; nt++)
#pragma unroll
            for (int j = 0; j < 4; j++) acc[mt][nt][j] = 0.f;

    mma_mainloop2<BN, NTW>(A, W, K, m0, n0, smf, smem_u32(smf),
                           tid, g, tg, wm, wn, acc);

#pragma unroll
    for (int nt = 0; nt < NTW; nt++) {
        float v0 = fmaxf(fmaxf(acc[0][nt][0], acc[0][nt][2]),
                         fmaxf(acc[1][nt][0], acc[1][nt][2]));
        float v1 = fmaxf(fmaxf(acc[0][nt][1], acc[0][nt][3]),
                         fmaxf(acc[1][nt][1], acc[1][nt][3]));
#pragma unroll
        for (int off = 4; off < 32; off <<= 1) {
            v0 = fmaxf(v0, __shfl_xor_sync(0xffffffffu, v0, off));
            v1 = fmaxf(v1, __shfl_xor_sync(0xffffffffu, v1, off));
        }
        if (g == 0) {
            int lcol = wn + nt * 8 + 2 * tg;
            if (PR == 32) {
                int center = blockIdx.x * 4 + (wid & 3);
                int col = n0 + lcol;
                dst[(size_t)center * N + col] =
                    fmaxf(v0 + __ldg(&bias[col]), 0.f);
                dst[(size_t)center * N + col + 1] =
                    fmaxf(v1 + __ldg(&bias[col + 1]), 0.f);
            } else {
                sbuf[wid & 3][lcol] = v0;
                sbuf[wid & 3][lcol + 1] = v1;
            }
        }
    }
    if (PR == 128) {
        __syncthreads();
        if (tid < BN) {
            float m = fmaxf(fmaxf(sbuf[0][tid], sbuf[1][tid]),
                            fmaxf(sbuf[2][tid], sbuf[3][tid]));
            int col = n0 + tid;
            dst[(size_t)blockIdx.x * N + col] =
                fmaxf(m + __ldg(&bias[col]), 0.f);
        }
    }
}

// ---------------------------------------------------------------------------
// L2_0 fused (R14 path, unchanged): A gathered from f1 during prefetch.
// ---------------------------------------------------------------------------
__global__ void __launch_bounds__(256) gemm_l20_fused(
    const float* __restrict__ f1, const float* __restrict__ W,
    const float* __restrict__ bias, float* __restrict__ C)
{
    constexpr int BN = 128, NTW = 8, KTOT = 160;
    constexpr int SLOT = (128 + BN) * ST;
    extern __shared__ float smf[];
    int*   sbase = (int*)(smf + 2 * SLOT);
    float* sxyz  = smf + 2 * SLOT + 128;

    const int tid = threadIdx.x;
    const int wid = tid >> 5, lane = tid & 31;
    const int g = lane >> 2, tg = lane & 3;
    const int wm = (wid & 3) * 32;
    const int wn = (wid >> 2) * 64;
    const int m0 = blockIdx.x * 128;
    const uint32_t smbase = smem_u32(smf);

    if (tid < 128) {
        int R = m0 + tid;
        int c = R >> 5;
        int b = c >> 7;
        int j = g_g2[R];
        int fj = b * S1 + j;
        sbase[tid] = fj * 128;
        sxyz[tid * 4 + 0] = g_nx1[fj * 3 + 0] - g_nx2[c * 3 + 0];
        sxyz[tid * 4 + 1] = g_nx1[fj * 3 + 1] - g_nx2[c * 3 + 1];
        sxyz[tid * 4 + 2] = g_nx1[fj * 3 + 2] - g_nx2[c * 3 + 2];
    }
    __syncthreads();

    auto prefetch = [&](int kc, int s) {
        const uint32_t sb = smbase + (uint32_t)(s * SLOT) * 4u;
        if (kc < 4) {
#pragma unroll
            for (int i = 0; i < 4; i++) {
                int seg = tid + i * 256;
                int r = seg >> 3, c16 = seg & 7;
                cp16(sb + (uint32_t)(r * ST + c16 * 4) * 4u,
                     f1 + (size_t)sbase[r] + kc * 32 + c16 * 4);
            }
        } else {
            float* dstA = smf + s * SLOT;
            for (int idx = tid; idx < 128 * 32; idx += 256) {
                int r = idx >> 5, col = idx & 31;
                dstA[r * ST + col] = (col < 3) ? sxyz[r * 4 + col] : 0.f;
            }
        }
#pragma unroll
        for (int i = 0; i < 4; i++) {
            int seg = tid + i * 256;
            int r = seg >> 3, c16 = seg & 7;
            cp16(sb + (uint32_t)((128 + r) * ST + c16 * 4) * 4u,
                 W + (size_t)r * KTOT + kc * 32 + c16 * 4);
        }
    };

    float acc[2][NTW][4];
#pragma unroll
    for (int mt = 0; mt < 2; mt++)
#pragma unroll
        for (int nt = 0; nt < NTW; nt++)
#pragma unroll
            for (int j = 0; j < 4; j++) acc[mt][nt][j] = 0.f;

    prefetch(0, 0);
    CP_COMMIT();

    for (int kc = 0; kc < 5; kc++) {
        if (kc + 1 < 5) prefetch(kc + 1, (kc + 1) & 1);
        CP_COMMIT();
        CP_WAIT1();
        __syncthreads();

        const float* s_a = smf + (kc & 1) * SLOT;
        const float* s_w = s_a + 128 * ST;

#pragma unroll
        for (int grp = 0; grp < 2; grp++) {
            const int kb = grp * 16;
            uint32_t ah[2][4], al[2][4];
            frag_a_bf16(s_a, wm, g, tg, kb, ah, al);
#pragma unroll
            for (int nt = 0; nt < NTW; nt++) {
                int n = wn + nt * 8 + g;
                bfrag_mma_bf16(s_w, n, kb, tg, ah, al, acc[0][nt], acc[1][nt]);
            }
        }
        __syncthreads();
    }

#pragma unroll
    for (int mt = 0; mt < 2; mt++) {
#pragma unroll
        for (int nt = 0; nt < NTW; nt++) {
            int row = m0 + wm + mt * 16 + g;
            int col = wn + nt * 8 + 2 * tg;
            float b0 = __ldg(&bias[col]);
            float b1 = __ldg(&bias[col + 1]);
            float2 o0, o1;
            o0.x = fmaxf(acc[mt][nt][0] + b0, 0.f);
            o0.y = fmaxf(acc[mt][nt][1] + b1, 0.f);
            o1.x = fmaxf(acc[mt][nt][2] + b0, 0.f);
            o1.y = fmaxf(acc[mt][nt][3] + b1, 0.f);
            *reinterpret_cast<float2*>(C + (size_t)row * 128 + col) = o0;
            *reinterpret_cast<float2*>(C + (size_t)(row + 8) * 128 + col) = o1;
        }
    }
}

// ---------------------------------------------------------------------------
static void run_mma(const float* A, const float* W, const float* bias,
                    float* C, int M, int N, int K)
{
    if (N % 128 == 0) {
        const int smem = (2 * 256 * 32 + 2 * 256 * 20) * 4;  // 106496
        cudaFuncSetAttribute(gemm_mma<128>,
                             cudaFuncAttributeMaxDynamicSharedMemorySize, smem);
        dim3 g(M / 128, N / 128);
        gemm_mma<128><<<g, 256, smem>>>(A, W, bias, C, M, N, K);
    } else {
        const int smem = (2 * 192 * 32 + 2 * 192 * 20) * 4;  // 79872
        cudaFuncSetAttribute(gemm_mma<64>,
                             cudaFuncAttributeMaxDynamicSharedMemorySize, smem);
        dim3 g(M / 128, N / 64);
        gemm_mma<64><<<g, 256, smem>>>(A, W, bias, C, M, N, K);
    }
}

template <int PR>
static void run_mma_pool(const float* A, const float* W, const float* bias,
                         float* dst, int M, int N, int K)
{
    const int smem = (2 * 256 * 32 + 2 * 256 * 20) * 4;      // 106496
    cudaFuncSetAttribute(gemm_mma_pool<128, PR>,
                         cudaFuncAttributeMaxDynamicSharedMemorySize, smem);
    dim3 g(M / 128, N / 128);
    gemm_mma_pool<128, PR><<<g, 256, smem>>>(A, W, bias, dst, M, N, K);
}

extern "C" void kernel_launch(void* const* d_in, const int* in_sizes, int n_in,
                              void* d_out, int out_size)
{
    (void)in_sizes; (void)n_in; (void)out_size;
    const float* data = (const float*)d_in[0];
    const float *w[9], *bi[9];
    for (int i = 0; i < 9; i++) {
        w[i]  = (const float*)d_in[1 + 2 * i];
        bi[i] = (const float*)d_in[2 + 2 * i];
    }

    float *scr0, *scr1, *f1, *f2, *nx1, *nx2, *x3, *w2p, *w3p;
    int *g2;
    cudaGetSymbolAddress((void**)&scr0, g_scr0);
    cudaGetSymbolAddress((void**)&scr1, g_scr1);
    cudaGetSymbolAddress((void**)&f1, g_f1);
    cudaGetSymbolAddress((void**)&f2, g_f2);
    cudaGetSymbolAddress((void**)&nx1, g_nx1);
    cudaGetSymbolAddress((void**)&nx2, g_nx2);
    cudaGetSymbolAddress((void**)&g2, g_g2);
    cudaGetSymbolAddress((void**)&x3, g_x3);
    cudaGetSymbolAddress((void**)&w2p, g_w2p);
    cudaGetSymbolAddress((void**)&w3p, g_w3p);

    const float R2a = (float)(0.2 * 0.2);
    const float R2b = (float)(0.4 * 0.4);

    padw2_reorder<<<(128 * 160 + 255) / 256, 256>>>(w[3], w2p);
    padw_kernel<<<(256 * 288 + 255) / 256, 256>>>(w[6], w3p, 256, 259, 288);

    // ---- Stage 1 ----
    fps_kernel<N1, S1, 512><<<BB, 512>>>(data, nx1);
    {
        const int smem = 3 * N1 * 4 + 32 * 32 * 4;   // 53248
        cudaFuncSetAttribute(ballq1_gather,
                             cudaFuncAttributeMaxDynamicSharedMemorySize, smem);
        ballq1_gather<<<BB * 8, 1024, smem>>>(data, nx1, R2a, scr1);
    }
    {
        const int smem = (2 * 128 * ST + 2 * 64 * ST + 128 * 4) * 4;  // 63488
        cudaFuncSetAttribute(gemm_l11_fused,
                             cudaFuncAttributeMaxDynamicSharedMemorySize, smem);
        gemm_l11_fused<<<(BB * S1 * NS) / 128, 256, smem>>>(
            scr1, w[0], bi[0], w[1], bi[1], scr0);
    }
    run_mma_pool<32>(scr0, w[2], bi[2], f1, BB * S1 * NS, 128, 64);

    // ---- Stage 2 ----
    fps2_ballq2<<<BB, 256>>>(nx1, nx2, R2b, g2);
    {
        const int smem = (2 * (128 + 128) * ST + 128 + 128 * 4) * 4;  // 84480
        cudaFuncSetAttribute(gemm_l20_fused,
                             cudaFuncAttributeMaxDynamicSharedMemorySize, smem);
        gemm_l20_fused<<<(BB * S2 * NS) / 128, 256, smem>>>(f1, w2p, bi[3], scr1);
    }
    run_mma(scr1, w[4], bi[4], scr0, BB * S2 * NS, 128, 128);
    run_mma_pool<32>(scr0, w[5], bi[5], f2, BB * S2 * NS, 256, 128);

    // ---- Stage 3 ----
    concat3_kernel<<<(BB * S2 * 288 + 255) / 256, 256>>>(x3);
    run_mma(x3, w3p, bi[6], scr0, BB * S2, 256, 288);
    run_mma(scr0, w[7], bi[7], scr1, BB * S2, 512, 256);
    run_mma_pool<128>(scr1, w[8], bi[8], (float*)d_out, BB * S2, 1024, 512);
}